// round 6
// baseline (speedup 1.0000x reference)
#include <cuda_runtime.h>
#include <cuda_fp16.h>
#include <cstdint>

#define T_TOKENS 4096
#define DDIM 1024
#define MDIM 2048
#define NEXP 8
#define ROWS_PAD 9216      // 72 tiles * 128 rows
#define MAX_TILES 72

// Block layout: all GEMM operands stored as 16KB blocks of (64 k) x (128 n/m),
// A blocks: 128 m x 64 k, element (m,k) at byte m*128 + ((k*2) ^ ((m&7)<<4))
// B blocks: 64 k x 128 n, element (k,n) at byte k*256 + ((n*2) ^ ((k&7)<<4))
__device__ __half g_Wg[NEXP * DDIM * MDIM];
__device__ __half g_Wu[NEXP * DDIM * MDIM];
__device__ __half g_Wo[NEXP * MDIM * DDIM];
__device__ __half g_X[ROWS_PAD * DDIM];
__device__ __half g_H[ROWS_PAD * MDIM];
__device__ float  g_Y[ROWS_PAD * DDIM];
__device__ int    g_counts[NEXP];
__device__ int    g_offsets[NEXP + 1];
__device__ int    g_tile_expert[MAX_TILES];
__device__ int    g_row_tok[ROWS_PAD];
__device__ int    g_tok_e[T_TOKENS * 2];
__device__ int    g_tok_slot[T_TOKENS * 2];
__device__ float  g_tok_w[T_TOKENS * 2];

// ---------------- helpers ----------------
__device__ __forceinline__ uint32_t smem_u32(const void* p) {
    uint32_t a;
    asm("{ .reg .u64 t; cvta.to.shared.u64 t, %1; cvt.u32.u64 %0, t; }" : "=r"(a) : "l"(p));
    return a;
}
__device__ __forceinline__ void mbar_init(uint32_t a, uint32_t cnt) {
    asm volatile("mbarrier.init.shared.b64 [%0], %1;" :: "r"(a), "r"(cnt) : "memory");
}
__device__ __forceinline__ void mbar_expect_tx(uint32_t a, uint32_t bytes) {
    asm volatile("mbarrier.arrive.expect_tx.shared.b64 _, [%0], %1;" :: "r"(a), "r"(bytes) : "memory");
}
__device__ __forceinline__ void bulk_g2s(uint32_t dst, const void* src, uint32_t bytes, uint32_t mbar) {
    asm volatile("cp.async.bulk.shared::cta.global.mbarrier::complete_tx::bytes [%0], [%1], %2, [%3];"
                 :: "r"(dst), "l"(src), "r"(bytes), "r"(mbar) : "memory");
}
__device__ __forceinline__ void mbar_wait(uint32_t a, uint32_t parity) {
    asm volatile(
        "{\n\t.reg .pred P1;\n\t"
        "W%=:\n\t"
        "mbarrier.try_wait.parity.acquire.cta.shared::cta.b64 P1, [%0], %1, 0x989680;\n\t"
        "@P1 bra.uni D%=;\n\t"
        "bra.uni W%=;\n\t"
        "D%=:\n\t}"
        :: "r"(a), "r"(parity) : "memory");
}
#define FENCE_ASYNC() asm volatile("fence.proxy.async.shared::cta;" ::: "memory")
__device__ __forceinline__ void ldm_x4(uint32_t* r, uint32_t addr) {
    asm volatile("ldmatrix.sync.aligned.m8n8.x4.shared.b16 {%0,%1,%2,%3}, [%4];"
                 : "=r"(r[0]), "=r"(r[1]), "=r"(r[2]), "=r"(r[3]) : "r"(addr));
}
__device__ __forceinline__ void ldm_x4_t(uint32_t* r, uint32_t addr) {
    asm volatile("ldmatrix.sync.aligned.m8n8.x4.trans.shared.b16 {%0,%1,%2,%3}, [%4];"
                 : "=r"(r[0]), "=r"(r[1]), "=r"(r[2]), "=r"(r[3]) : "r"(addr));
}
__device__ __forceinline__ void mma16816(float* c, const uint32_t* a, const uint32_t* b) {
    asm volatile(
        "mma.sync.aligned.m16n8k16.row.col.f32.f16.f16.f32 "
        "{%0,%1,%2,%3}, {%4,%5,%6,%7}, {%8,%9}, {%0,%1,%2,%3};"
        : "+f"(c[0]), "+f"(c[1]), "+f"(c[2]), "+f"(c[3])
        : "r"(a[0]), "r"(a[1]), "r"(a[2]), "r"(a[3]), "r"(b[0]), "r"(b[1]));
}

// ---------------- init ----------------
__global__ void init_kernel() {
    int i = blockIdx.x * blockDim.x + threadIdx.x;
    if (i < NEXP) g_counts[i] = 0;
    if (i < ROWS_PAD) g_row_tok[i] = -1;
}

// ---------------- convert: fp32 [E][K][N] -> tiled+swizzled fp16 B-blocks ----------------
__global__ void convert_kernel(const float* __restrict__ wg,
                               const float* __restrict__ wu,
                               const float* __restrict__ wo) {
    __shared__ float tile[64][128];
    const float* src;
    __half* dst;
    int KD, ND;
    if (blockIdx.y == 0)      { src = wg; dst = g_Wg; KD = DDIM; ND = MDIM; }
    else if (blockIdx.y == 1) { src = wu; dst = g_Wu; KD = DDIM; ND = MDIM; }
    else                      { src = wo; dst = g_Wo; KD = MDIM; ND = DDIM; }
    int NT = ND / 128, KT = KD / 64;
    int x = blockIdx.x;                 // e*NT*KT + nt*KT + kt   (2048 for all)
    int e = x / (NT * KT);
    int nt = (x / KT) % NT;
    int kt = x % KT;
    int k0 = kt * 64, n0 = nt * 128;
    int tid = threadIdx.x;              // 256
    const float* s = src + (size_t)e * KD * ND;
    #pragma unroll
    for (int i = 0; i < 8; i++) {
        int idx = tid + i * 256;        // 2048 float4
        int k = idx >> 5, nq = (idx & 31) * 4;
        float4 v = *reinterpret_cast<const float4*>(s + (size_t)(k0 + k) * ND + n0 + nq);
        *reinterpret_cast<float4*>(&tile[k][nq]) = v;
    }
    __syncthreads();
    uint4* out = reinterpret_cast<uint4*>(dst + (size_t)x * 8192);
    #pragma unroll
    for (int i = 0; i < 4; i++) {
        int idx = tid + i * 256;        // 1024 uint4
        int b16 = idx * 16;
        int k = b16 >> 8;
        int n = ((b16 & 255) ^ ((k & 7) << 4)) >> 1;
        __half2 h[4];
        #pragma unroll
        for (int q = 0; q < 4; q++)
            h[q] = __floats2half2_rn(tile[k][n + 2 * q], tile[k][n + 2 * q + 1]);
        out[idx] = *reinterpret_cast<uint4*>(h);
    }
}

// ---------------- router: thread-per-token, Wr in smem ----------------
#define RT_THREADS 128
__global__ void router_kernel(const float* __restrict__ residual,
                              const float* __restrict__ Wr) {
    __shared__ float wrs[DDIM * NEXP];   // 32 KB
    int tid = threadIdx.x;
    #pragma unroll
    for (int i = 0; i < 16; i++) {       // 2048 float4
        int idx = tid + i * RT_THREADS;
        reinterpret_cast<float4*>(wrs)[idx] = reinterpret_cast<const float4*>(Wr)[idx];
    }
    __syncthreads();
    int t = blockIdx.x * RT_THREADS + tid;
    const float4* xr = reinterpret_cast<const float4*>(residual + (size_t)t * DDIM);
    float acc[NEXP];
    #pragma unroll
    for (int e = 0; e < NEXP; e++) acc[e] = 0.f;
    #pragma unroll 4
    for (int q = 0; q < 256; q++) {
        float4 xv = xr[q];
        const float4* w0 = reinterpret_cast<const float4*>(wrs + q * 4 * NEXP);
        #pragma unroll
        for (int r = 0; r < 4; r++) {
            float xs = (&xv.x)[r];
            float4 wa = w0[r * 2], wb = w0[r * 2 + 1];
            acc[0] += xs * wa.x; acc[1] += xs * wa.y; acc[2] += xs * wa.z; acc[3] += xs * wa.w;
            acc[4] += xs * wb.x; acc[5] += xs * wb.y; acc[6] += xs * wb.z; acc[7] += xs * wb.w;
        }
    }
    // softmax + top2 + renorm
    float mx = acc[0];
    #pragma unroll
    for (int e = 1; e < NEXP; e++) mx = fmaxf(mx, acc[e]);
    float p[NEXP]; float sum = 0.f;
    #pragma unroll
    for (int e = 0; e < NEXP; e++) { p[e] = expf(acc[e] - mx); sum += p[e]; }
    #pragma unroll
    for (int e = 0; e < NEXP; e++) p[e] /= sum;
    int i1 = 0;
    #pragma unroll
    for (int e = 1; e < NEXP; e++) if (p[e] > p[i1]) i1 = e;
    int i2 = -1;
    #pragma unroll
    for (int e = 0; e < NEXP; e++) {
        if (e == i1) continue;
        if (i2 < 0 || p[e] > p[i2]) i2 = e;
    }
    float w1 = p[i1], w2 = p[i2];
    float inv = 1.f / (w1 + w2 + 1e-8f);
    w1 *= inv; w2 *= inv;
    int s1 = atomicAdd(&g_counts[i1], 1);
    int s2 = atomicAdd(&g_counts[i2], 1);
    g_tok_e[2 * t] = i1;     g_tok_e[2 * t + 1] = i2;
    g_tok_slot[2 * t] = s1;  g_tok_slot[2 * t + 1] = s2;
    g_tok_w[2 * t] = w1;     g_tok_w[2 * t + 1] = w2;
}

__global__ void scan_kernel() {
    int off = 0, tile = 0;
    for (int e = 0; e < NEXP; e++) {
        g_offsets[e] = off;
        int nt = (g_counts[e] + 127) / 128;
        for (int k = 0; k < nt; k++) g_tile_expert[tile++] = e;
        off += nt * 128;
    }
    g_offsets[NEXP] = off;
    for (; tile < MAX_TILES; tile++) g_tile_expert[tile] = -1;
}

__global__ void scatter_kernel() {
    int i = blockIdx.x * blockDim.x + threadIdx.x;
    if (i >= T_TOKENS * 2) return;
    int e = g_tok_e[i];
    int row = g_offsets[e] + g_tok_slot[i];
    g_row_tok[row] = i >> 1;
}

// gather -> A-block layout (zero pads)
__global__ void gather_kernel(const float* __restrict__ residual) {
    int row = blockIdx.x;
    int c = threadIdx.x * 8;            // 128 threads, 8 cols each
    int tok = g_row_tok[row];
    __half2 h[4];
    if (tok < 0) {
        __half2 z = __half2half2(__float2half(0.f));
        h[0] = z; h[1] = z; h[2] = z; h[3] = z;
    } else {
        const float4* src = reinterpret_cast<const float4*>(residual + (size_t)tok * DDIM + c);
        float4 a = src[0], b = src[1];
        h[0] = __floats2half2_rn(a.x, a.y); h[1] = __floats2half2_rn(a.z, a.w);
        h[2] = __floats2half2_rn(b.x, b.y); h[3] = __floats2half2_rn(b.z, b.w);
    }
    int rt = row >> 7, m = row & 127;
    int kt = c >> 6, k = c & 63;
    reinterpret_cast<uint4*>(g_X)[(size_t)(rt * 16 + kt) * 1024 + m * 8 + ((k >> 3) ^ (m & 7))] =
        *reinterpret_cast<uint4*>(h);
}

// ================= GEMM1: fused gate+up, 128x128, BK=64, 4-stage bulk pipeline =================
#define G1_STG 4
#define G1_NC 16
#define G1_STAGE_B 49152
#define G1_SMEM (1024 + G1_STG * G1_STAGE_B)

__global__ void __launch_bounds__(256) gemm1_kernel(const float* __restrict__ bg,
                                                    const float* __restrict__ bu) {
    int e = g_tile_expert[blockIdx.y];
    if (e < 0) return;
    int rt = blockIdx.y, nt_ = blockIdx.x;
    int row0 = rt * 128, n0 = nt_ * 128;
    extern __shared__ char smc[];
    uint32_t sb = smem_u32(smc);
    int tid = threadIdx.x, lane = tid & 31, w = tid >> 5;
    int wm = w >> 2, wn = w & 3;        // 2x4 warps, 64x32 each

    const char* Ablk  = (const char*)g_X  + (size_t)(rt * 16) * 16384;
    const char* Bgblk = (const char*)g_Wg + (size_t)((e * 16 + nt_) * 16) * 16384;
    const char* Bublk = (const char*)g_Wu + (size_t)((e * 16 + nt_) * 16) * 16384;

    if (tid == 0) {
        #pragma unroll
        for (int s = 0; s < G1_STG; s++) mbar_init(sb + 8 * s, 1);
    }
    __syncthreads();
    FENCE_ASYNC();

    auto issue = [&](int c) {
        int b = c % G1_STG;
        uint32_t mb = sb + 8 * b;
        uint32_t dst = sb + 1024 + b * G1_STAGE_B;
        mbar_expect_tx(mb, G1_STAGE_B);
        bulk_g2s(dst,          Ablk  + (size_t)c * 16384, 16384, mb);
        bulk_g2s(dst + 16384,  Bgblk + (size_t)c * 16384, 16384, mb);
        bulk_g2s(dst + 32768,  Bublk + (size_t)c * 16384, 16384, mb);
    };
    if (tid == 0) {
        #pragma unroll
        for (int s = 0; s < G1_STG; s++) issue(s);
    }

    float accG[4][4][4], accU[4][4][4];
    #pragma unroll
    for (int mt = 0; mt < 4; mt++)
        #pragma unroll
        for (int nt = 0; nt < 4; nt++)
            #pragma unroll
            for (int q = 0; q < 4; q++) { accG[mt][nt][q] = 0.f; accU[mt][nt][q] = 0.f; }

    for (int c = 0; c < G1_NC; c++) {
        mbar_wait(sb + 8 * (c % G1_STG), (c / G1_STG) & 1);
        uint32_t Ab = sb + 1024 + (c % G1_STG) * G1_STAGE_B;
        uint32_t Bgb = Ab + 16384, Bub = Ab + 32768;
        #pragma unroll
        for (int kk = 0; kk < 64; kk += 16) {
            uint32_t a[4][4];
            #pragma unroll
            for (int mt = 0; mt < 4; mt++) {
                int m = wm * 64 + mt * 16 + (lane & 15);
                int colk = kk + (lane >> 4) * 8;
                ldm_x4(a[mt], Ab + m * 128 + ((colk * 2) ^ ((m & 7) << 4)));
            }
            uint32_t bG[2][4], bU[2][4];
            #pragma unroll
            for (int p = 0; p < 2; p++) {
                int krow = kk + (lane & 15);
                int coln = wn * 32 + p * 16 + (lane >> 4) * 8;
                uint32_t off = krow * 256 + ((coln * 2) ^ ((krow & 7) << 4));
                ldm_x4_t(bG[p], Bgb + off);
                ldm_x4_t(bU[p], Bub + off);
            }
            #pragma unroll
            for (int mt = 0; mt < 4; mt++)
                #pragma unroll
                for (int nt = 0; nt < 4; nt++) {
                    mma16816(accG[mt][nt], a[mt], &bG[nt >> 1][(nt & 1) * 2]);
                    mma16816(accU[mt][nt], a[mt], &bU[nt >> 1][(nt & 1) * 2]);
                }
        }
        __syncthreads();
        if (tid == 0 && c + G1_STG < G1_NC) issue(c + G1_STG);
    }

    // epilogue: h = silu(g+bg)*(u+bu) -> fp16 H in A-block layout
    const float* bgp = bg + e * MDIM + n0 + wn * 32;
    const float* bup = bu + e * MDIM + n0 + wn * 32;
    #pragma unroll
    for (int nt = 0; nt < 4; nt++) {
        int colb = nt * 8 + (lane & 3) * 2;
        float b_g0 = bgp[colb], b_g1 = bgp[colb + 1];
        float b_u0 = bup[colb], b_u1 = bup[colb + 1];
        int col = n0 + wn * 32 + colb;          // global H column
        int kt = col >> 6, k2 = (col & 63) * 2;
        size_t blk = (size_t)(rt * 32 + kt) * 16384;
        #pragma unroll
        for (int mt = 0; mt < 4; mt++) {
            int m = wm * 64 + mt * 16 + (lane >> 2);
            float g0 = accG[mt][nt][0] + b_g0, g1 = accG[mt][nt][1] + b_g1;
            float u0 = accU[mt][nt][0] + b_u0, u1 = accU[mt][nt][1] + b_u1;
            float h0 = g0 / (1.f + __expf(-g0)) * u0;
            float h1 = g1 / (1.f + __expf(-g1)) * u1;
            *reinterpret_cast<__half2*>((char*)g_H + blk + m * 128 + (k2 ^ ((m & 7) << 4))) =
                __floats2half2_rn(h0, h1);
            int m2 = m + 8;
            float g2 = accG[mt][nt][2] + b_g0, g3 = accG[mt][nt][3] + b_g1;
            float u2 = accU[mt][nt][2] + b_u0, u3 = accU[mt][nt][3] + b_u1;
            float h2 = g2 / (1.f + __expf(-g2)) * u2;
            float h3 = g3 / (1.f + __expf(-g3)) * u3;
            *reinterpret_cast<__half2*>((char*)g_H + blk + m2 * 128 + (k2 ^ ((m2 & 7) << 4))) =
                __floats2half2_rn(h2, h3);
        }
    }
}

// ================= GEMM2: H @ W_out -> Y fp32, 128x128, BK=64, 4-stage bulk pipeline =================
#define G2_STG 4
#define G2_NC 32
#define G2_STAGE_B 32768
#define G2_SMEM (1024 + G2_STG * G2_STAGE_B)

__global__ void __launch_bounds__(256) gemm2_kernel() {
    int e = g_tile_expert[blockIdx.y];
    if (e < 0) return;
    int rt = blockIdx.y, nt_ = blockIdx.x;
    int row0 = rt * 128, n0 = nt_ * 128;
    extern __shared__ char smc[];
    uint32_t sb = smem_u32(smc);
    int tid = threadIdx.x, lane = tid & 31, w = tid >> 5;
    int wm = w >> 2, wn = w & 3;

    const char* Ablk = (const char*)g_H  + (size_t)(rt * 32) * 16384;
    const char* Bblk = (const char*)g_Wo + (size_t)((e * 8 + nt_) * 32) * 16384;

    if (tid == 0) {
        #pragma unroll
        for (int s = 0; s < G2_STG; s++) mbar_init(sb + 8 * s, 1);
    }
    __syncthreads();
    FENCE_ASYNC();

    auto issue = [&](int c) {
        int b = c % G2_STG;
        uint32_t mb = sb + 8 * b;
        uint32_t dst = sb + 1024 + b * G2_STAGE_B;
        mbar_expect_tx(mb, G2_STAGE_B);
        bulk_g2s(dst,         Ablk + (size_t)c * 16384, 16384, mb);
        bulk_g2s(dst + 16384, Bblk + (size_t)c * 16384, 16384, mb);
    };
    if (tid == 0) { issue(0); issue(1); issue(2); issue(3); }

    float acc[4][4][4];
    #pragma unroll
    for (int mt = 0; mt < 4; mt++)
        #pragma unroll
        for (int nt = 0; nt < 4; nt++)
            #pragma unroll
            for (int q = 0; q < 4; q++) acc[mt][nt][q] = 0.f;

    for (int c = 0; c < G2_NC; c++) {
        mbar_wait(sb + 8 * (c % G2_STG), (c / G2_STG) & 1);
        uint32_t Ab = sb + 1024 + (c % G2_STG) * G2_STAGE_B;
        uint32_t Bb = Ab + 16384;
        #pragma unroll
        for (int kk = 0; kk < 64; kk += 16) {
            uint32_t a[4][4];
            #pragma unroll
            for (int mt = 0; mt < 4; mt++) {
                int m = wm * 64 + mt * 16 + (lane & 15);
                int colk = kk + (lane >> 4) * 8;
                ldm_x4(a[mt], Ab + m * 128 + ((colk * 2) ^ ((m & 7) << 4)));
            }
            uint32_t bB[2][4];
            #pragma unroll
            for (int p = 0; p < 2; p++) {
                int krow = kk + (lane & 15);
                int coln = wn * 32 + p * 16 + (lane >> 4) * 8;
                ldm_x4_t(bB[p], Bb + krow * 256 + ((coln * 2) ^ ((krow & 7) << 4)));
            }
            #pragma unroll
            for (int mt = 0; mt < 4; mt++)
                #pragma unroll
                for (int nt = 0; nt < 4; nt++)
                    mma16816(acc[mt][nt], a[mt], &bB[nt >> 1][(nt & 1) * 2]);
        }
        __syncthreads();
        if (tid == 0 && c + G2_STG < G2_NC) issue(c + G2_STG);
    }

    // epilogue: fp32 Y store (linear)
    #pragma unroll
    for (int nt = 0; nt < 4; nt++) {
        int colb = nt * 8 + (lane & 3) * 2;
        int col = n0 + wn * 32 + colb;
        #pragma unroll
        for (int mt = 0; mt < 4; mt++) {
            int row = row0 + wm * 64 + mt * 16 + (lane >> 2);
            float2 v0 = make_float2(acc[mt][nt][0], acc[mt][nt][1]);
            float2 v1 = make_float2(acc[mt][nt][2], acc[mt][nt][3]);
            *reinterpret_cast<float2*>(g_Y + (size_t)row * DDIM + col) = v0;
            *reinterpret_cast<float2*>(g_Y + (size_t)(row + 8) * DDIM + col) = v1;
        }
    }
}

// ---------------- combine ----------------
__global__ void combine_kernel(float* __restrict__ out, const float* __restrict__ bo) {
    int t = blockIdx.x;
    int c = threadIdx.x * 4;
    int e1 = g_tok_e[2 * t], e2 = g_tok_e[2 * t + 1];
    int r1 = g_offsets[e1] + g_tok_slot[2 * t];
    int r2 = g_offsets[e2] + g_tok_slot[2 * t + 1];
    float w1 = g_tok_w[2 * t], w2 = g_tok_w[2 * t + 1];
    float4 y1 = *reinterpret_cast<const float4*>(&g_Y[(size_t)r1 * DDIM + c]);
    float4 y2 = *reinterpret_cast<const float4*>(&g_Y[(size_t)r2 * DDIM + c]);
    float4 b1 = *reinterpret_cast<const float4*>(&bo[e1 * DDIM + c]);
    float4 b2 = *reinterpret_cast<const float4*>(&bo[e2 * DDIM + c]);
    float4 o;
    o.x = w1 * (y1.x + b1.x) + w2 * (y2.x + b2.x);
    o.y = w1 * (y1.y + b1.y) + w2 * (y2.y + b2.y);
    o.z = w1 * (y1.z + b1.z) + w2 * (y2.z + b2.z);
    o.w = w1 * (y1.w + b1.w) + w2 * (y2.w + b2.w);
    *reinterpret_cast<float4*>(&out[(size_t)t * DDIM + c]) = o;
}

// ---------------- launch ----------------
extern "C" void kernel_launch(void* const* d_in, const int* in_sizes, int n_in,
                              void* d_out, int out_size) {
    const float* residual = (const float*)d_in[0];
    const float* Wr = (const float*)d_in[1];
    const float* Wg = (const float*)d_in[2];
    const float* bg = (const float*)d_in[3];
    const float* Wu = (const float*)d_in[4];
    const float* bu = (const float*)d_in[5];
    const float* Wo = (const float*)d_in[6];
    const float* bo = (const float*)d_in[7];
    float* out = (float*)d_out;

    static bool attr_set = false;
    if (!attr_set) {
        cudaFuncSetAttribute(gemm1_kernel, cudaFuncAttributeMaxDynamicSharedMemorySize, G1_SMEM);
        cudaFuncSetAttribute(gemm2_kernel, cudaFuncAttributeMaxDynamicSharedMemorySize, G2_SMEM);
        attr_set = true;
    }

    init_kernel<<<(ROWS_PAD + 255) / 256, 256>>>();
    dim3 cg(2048, 3);
    convert_kernel<<<cg, 256>>>(Wg, Wu, Wo);
    router_kernel<<<T_TOKENS / RT_THREADS, RT_THREADS>>>(residual, Wr);
    scan_kernel<<<1, 1>>>();
    scatter_kernel<<<(T_TOKENS * 2 + 255) / 256, 256>>>();
    gather_kernel<<<ROWS_PAD, 128>>>(residual);
    dim3 g1(MDIM / 128, MAX_TILES);
    gemm1_kernel<<<g1, 256, G1_SMEM>>>(bg, bu);
    dim3 g2(DDIM / 128, MAX_TILES);
    gemm2_kernel<<<g2, 256, G2_SMEM>>>();
    combine_kernel<<<T_TOKENS, 256>>>(out, bo);
}

// round 7
// speedup vs baseline: 1.0871x; 1.0871x over previous
#include <cuda_runtime.h>
#include <cuda_fp16.h>
#include <cstdint>

#define T_TOKENS 4096
#define DDIM 1024
#define MDIM 2048
#define NEXP 8
#define ROWS_PAD 9216      // 72 tiles * 128 rows
#define MAX_TILES 72

// Block layout: all GEMM operands stored as 16KB blocks of (64 k) x (128 n/m),
// A blocks: 128 m x 64 k, element (m,k) at byte m*128 + ((k*2) ^ ((m&7)<<4))
// B blocks: 64 k x 128 n, element (k,n) at byte k*256 + ((n*2) ^ ((k&7)<<4))
__device__ __half g_Wg[NEXP * DDIM * MDIM];
__device__ __half g_Wu[NEXP * DDIM * MDIM];
__device__ __half g_Wo[NEXP * MDIM * DDIM];
__device__ __half g_X[ROWS_PAD * DDIM];
__device__ __half g_H[ROWS_PAD * MDIM];
__device__ float  g_Y[ROWS_PAD * DDIM];
__device__ int    g_counts[NEXP];
__device__ int    g_offsets[NEXP + 1];
__device__ int    g_tile_expert[MAX_TILES];
__device__ int    g_row_tok[ROWS_PAD];
__device__ int    g_tok_e[T_TOKENS * 2];
__device__ int    g_tok_slot[T_TOKENS * 2];
__device__ float  g_tok_w[T_TOKENS * 2];

// ---------------- helpers ----------------
__device__ __forceinline__ uint32_t smem_u32(const void* p) {
    uint32_t a;
    asm("{ .reg .u64 t; cvta.to.shared.u64 t, %1; cvt.u32.u64 %0, t; }" : "=r"(a) : "l"(p));
    return a;
}
__device__ __forceinline__ void mbar_init(uint32_t a, uint32_t cnt) {
    asm volatile("mbarrier.init.shared.b64 [%0], %1;" :: "r"(a), "r"(cnt) : "memory");
}
__device__ __forceinline__ void mbar_expect_tx(uint32_t a, uint32_t bytes) {
    asm volatile("mbarrier.arrive.expect_tx.shared.b64 _, [%0], %1;" :: "r"(a), "r"(bytes) : "memory");
}
__device__ __forceinline__ void bulk_g2s(uint32_t dst, const void* src, uint32_t bytes, uint32_t mbar) {
    asm volatile("cp.async.bulk.shared::cta.global.mbarrier::complete_tx::bytes [%0], [%1], %2, [%3];"
                 :: "r"(dst), "l"(src), "r"(bytes), "r"(mbar) : "memory");
}
__device__ __forceinline__ void mbar_wait(uint32_t a, uint32_t parity) {
    asm volatile(
        "{\n\t.reg .pred P1;\n\t"
        "W%=:\n\t"
        "mbarrier.try_wait.parity.acquire.cta.shared::cta.b64 P1, [%0], %1, 0x989680;\n\t"
        "@P1 bra.uni D%=;\n\t"
        "bra.uni W%=;\n\t"
        "D%=:\n\t}"
        :: "r"(a), "r"(parity) : "memory");
}
#define FENCE_ASYNC() asm volatile("fence.proxy.async.shared::cta;" ::: "memory")
__device__ __forceinline__ void ldm_x4(uint32_t* r, uint32_t addr) {
    asm volatile("ldmatrix.sync.aligned.m8n8.x4.shared.b16 {%0,%1,%2,%3}, [%4];"
                 : "=r"(r[0]), "=r"(r[1]), "=r"(r[2]), "=r"(r[3]) : "r"(addr));
}
__device__ __forceinline__ void ldm_x4_t(uint32_t* r, uint32_t addr) {
    asm volatile("ldmatrix.sync.aligned.m8n8.x4.trans.shared.b16 {%0,%1,%2,%3}, [%4];"
                 : "=r"(r[0]), "=r"(r[1]), "=r"(r[2]), "=r"(r[3]) : "r"(addr));
}
__device__ __forceinline__ void mma16816(float* c, const uint32_t* a, const uint32_t* b) {
    asm volatile(
        "mma.sync.aligned.m16n8k16.row.col.f32.f16.f16.f32 "
        "{%0,%1,%2,%3}, {%4,%5,%6,%7}, {%8,%9}, {%0,%1,%2,%3};"
        : "+f"(c[0]), "+f"(c[1]), "+f"(c[2]), "+f"(c[3])
        : "r"(a[0]), "r"(a[1]), "r"(a[2]), "r"(a[3]), "r"(b[0]), "r"(b[1]));
}

// ---------------- init ----------------
__global__ void init_kernel() {
    int i = blockIdx.x * blockDim.x + threadIdx.x;
    if (i < NEXP) g_counts[i] = 0;
    if (i < ROWS_PAD) g_row_tok[i] = -1;
}

// ---------------- convert: fp32 [E][K][N] -> tiled+swizzled fp16 B-blocks ----------------
__global__ void convert_kernel(const float* __restrict__ wg,
                               const float* __restrict__ wu,
                               const float* __restrict__ wo) {
    __shared__ float tile[64][128];
    const float* src;
    __half* dst;
    int KD, ND;
    if (blockIdx.y == 0)      { src = wg; dst = g_Wg; KD = DDIM; ND = MDIM; }
    else if (blockIdx.y == 1) { src = wu; dst = g_Wu; KD = DDIM; ND = MDIM; }
    else                      { src = wo; dst = g_Wo; KD = MDIM; ND = DDIM; }
    int NT = ND / 128, KT = KD / 64;
    int x = blockIdx.x;                 // e*NT*KT + nt*KT + kt   (2048 for all)
    int e = x / (NT * KT);
    int nt = (x / KT) % NT;
    int kt = x % KT;
    int k0 = kt * 64, n0 = nt * 128;
    int tid = threadIdx.x;              // 256
    const float* s = src + (size_t)e * KD * ND;
    #pragma unroll
    for (int i = 0; i < 8; i++) {
        int idx = tid + i * 256;        // 2048 float4
        int k = idx >> 5, nq = (idx & 31) * 4;
        float4 v = *reinterpret_cast<const float4*>(s + (size_t)(k0 + k) * ND + n0 + nq);
        *reinterpret_cast<float4*>(&tile[k][nq]) = v;
    }
    __syncthreads();
    uint4* out = reinterpret_cast<uint4*>(dst + (size_t)x * 8192);
    #pragma unroll
    for (int i = 0; i < 4; i++) {
        int idx = tid + i * 256;        // 1024 uint4
        int b16 = idx * 16;
        int k = b16 >> 8;
        int n = ((b16 & 255) ^ ((k & 7) << 4)) >> 1;
        __half2 h[4];
        #pragma unroll
        for (int q = 0; q < 4; q++)
            h[q] = __floats2half2_rn(tile[k][n + 2 * q], tile[k][n + 2 * q + 1]);
        out[idx] = *reinterpret_cast<uint4*>(h);
    }
}

// ---------------- router: block-per-token (coalesced; known-good R5 version) ----------------
__global__ void router_kernel(const float* __restrict__ residual,
                              const float* __restrict__ Wr) {
    int t = blockIdx.x;
    __shared__ float xs[DDIM];
    __shared__ float logits[NEXP];
    int tid = threadIdx.x;
    const float* x = residual + (size_t)t * DDIM;
    for (int i = tid; i < DDIM; i += 256) xs[i] = x[i];
    __syncthreads();
    int w = tid >> 5, lane = tid & 31;
    float s = 0.f;
    for (int i = lane; i < DDIM; i += 32) s += xs[i] * Wr[i * NEXP + w];
    #pragma unroll
    for (int o = 16; o > 0; o >>= 1) s += __shfl_xor_sync(0xffffffff, s, o);
    if (lane == 0) logits[w] = s;
    __syncthreads();
    if (tid == 0) {
        float mx = logits[0];
        #pragma unroll
        for (int e = 1; e < NEXP; e++) mx = fmaxf(mx, logits[e]);
        float p[NEXP]; float sum = 0.f;
        #pragma unroll
        for (int e = 0; e < NEXP; e++) { p[e] = expf(logits[e] - mx); sum += p[e]; }
        #pragma unroll
        for (int e = 0; e < NEXP; e++) p[e] /= sum;
        int i1 = 0;
        #pragma unroll
        for (int e = 1; e < NEXP; e++) if (p[e] > p[i1]) i1 = e;
        int i2 = -1;
        #pragma unroll
        for (int e = 0; e < NEXP; e++) {
            if (e == i1) continue;
            if (i2 < 0 || p[e] > p[i2]) i2 = e;
        }
        float w1 = p[i1], w2 = p[i2];
        float inv = 1.f / (w1 + w2 + 1e-8f);
        w1 *= inv; w2 *= inv;
        int s1 = atomicAdd(&g_counts[i1], 1);
        int s2 = atomicAdd(&g_counts[i2], 1);
        g_tok_e[2 * t] = i1;     g_tok_e[2 * t + 1] = i2;
        g_tok_slot[2 * t] = s1;  g_tok_slot[2 * t + 1] = s2;
        g_tok_w[2 * t] = w1;     g_tok_w[2 * t + 1] = w2;
    }
}

// ---------------- scatter with inline scan (tests R4's fusion in isolation) ----------------
__global__ void scatter_kernel() {
    int i = blockIdx.x * blockDim.x + threadIdx.x;
    if (i == 0) {   // publish arrays for gemm/combine (unchanged consumers)
        int off = 0, tile = 0;
        #pragma unroll
        for (int e = 0; e < NEXP; e++) {
            g_offsets[e] = off;
            int nt = (g_counts[e] + 127) >> 7;
            for (int k = 0; k < nt; k++) g_tile_expert[tile++] = e;
            off += nt << 7;
        }
        g_offsets[NEXP] = off;
        for (; tile < MAX_TILES; tile++) g_tile_expert[tile] = -1;
    }
    if (i >= T_TOKENS * 2) return;
    int e = g_tok_e[i];
    int off = 0;
    #pragma unroll
    for (int q = 0; q < NEXP; q++)
        if (q < e) off += ((g_counts[q] + 127) >> 7) << 7;
    g_row_tok[off + g_tok_slot[i]] = i >> 1;
}

// gather -> A-block layout (zero pads)
__global__ void gather_kernel(const float* __restrict__ residual) {
    int row = blockIdx.x;
    int c = threadIdx.x * 8;            // 128 threads, 8 cols each
    int tok = g_row_tok[row];
    __half2 h[4];
    if (tok < 0) {
        __half2 z = __half2half2(__float2half(0.f));
        h[0] = z; h[1] = z; h[2] = z; h[3] = z;
    } else {
        const float4* src = reinterpret_cast<const float4*>(residual + (size_t)tok * DDIM + c);
        float4 a = src[0], b = src[1];
        h[0] = __floats2half2_rn(a.x, a.y); h[1] = __floats2half2_rn(a.z, a.w);
        h[2] = __floats2half2_rn(b.x, b.y); h[3] = __floats2half2_rn(b.z, b.w);
    }
    int rt = row >> 7, m = row & 127;
    int kt = c >> 6, k = c & 63;
    reinterpret_cast<uint4*>(g_X)[(size_t)(rt * 16 + kt) * 1024 + m * 8 + ((k >> 3) ^ (m & 7))] =
        *reinterpret_cast<uint4*>(h);
}

// ================= GEMM1: fused gate+up, 128x128, BK=64, 3-stage bulk pipeline =================
#define G1_STG 3
#define G1_NC 16
#define G1_STAGE_B 49152
#define G1_SMEM (1024 + G1_STG * G1_STAGE_B)

__global__ void __launch_bounds__(256) gemm1_kernel(const float* __restrict__ bg,
                                                    const float* __restrict__ bu) {
    int e = g_tile_expert[blockIdx.y];
    if (e < 0) return;
    int rt = blockIdx.y, nt_ = blockIdx.x;
    int row0 = rt * 128, n0 = nt_ * 128;
    extern __shared__ char smc[];
    uint32_t sb = smem_u32(smc);
    int tid = threadIdx.x, lane = tid & 31, w = tid >> 5;
    int wm = w >> 2, wn = w & 3;        // 2x4 warps, 64x32 each

    const char* Ablk  = (const char*)g_X  + (size_t)(rt * 16) * 16384;
    const char* Bgblk = (const char*)g_Wg + (size_t)((e * 16 + nt_) * 16) * 16384;
    const char* Bublk = (const char*)g_Wu + (size_t)((e * 16 + nt_) * 16) * 16384;

    if (tid == 0) {
        #pragma unroll
        for (int s = 0; s < G1_STG; s++) mbar_init(sb + 8 * s, 1);
    }
    __syncthreads();
    FENCE_ASYNC();

    auto issue = [&](int c) {
        int b = c % G1_STG;
        uint32_t mb = sb + 8 * b;
        uint32_t dst = sb + 1024 + b * G1_STAGE_B;
        mbar_expect_tx(mb, G1_STAGE_B);
        bulk_g2s(dst,          Ablk  + (size_t)c * 16384, 16384, mb);
        bulk_g2s(dst + 16384,  Bgblk + (size_t)c * 16384, 16384, mb);
        bulk_g2s(dst + 32768,  Bublk + (size_t)c * 16384, 16384, mb);
    };
    if (tid == 0) { issue(0); issue(1); issue(2); }

    float accG[4][4][4], accU[4][4][4];
    #pragma unroll
    for (int mt = 0; mt < 4; mt++)
        #pragma unroll
        for (int nt = 0; nt < 4; nt++)
            #pragma unroll
            for (int q = 0; q < 4; q++) { accG[mt][nt][q] = 0.f; accU[mt][nt][q] = 0.f; }

    for (int c = 0; c < G1_NC; c++) {
        mbar_wait(sb + 8 * (c % G1_STG), (c / G1_STG) & 1);
        uint32_t Ab = sb + 1024 + (c % G1_STG) * G1_STAGE_B;
        uint32_t Bgb = Ab + 16384, Bub = Ab + 32768;
        #pragma unroll
        for (int kk = 0; kk < 64; kk += 16) {
            uint32_t a[4][4];
            #pragma unroll
            for (int mt = 0; mt < 4; mt++) {
                int m = wm * 64 + mt * 16 + (lane & 15);
                int colk = kk + (lane >> 4) * 8;
                ldm_x4(a[mt], Ab + m * 128 + ((colk * 2) ^ ((m & 7) << 4)));
            }
            uint32_t bG[2][4], bU[2][4];
            #pragma unroll
            for (int p = 0; p < 2; p++) {
                int krow = kk + (lane & 15);
                int coln = wn * 32 + p * 16 + (lane >> 4) * 8;
                uint32_t off = krow * 256 + ((coln * 2) ^ ((krow & 7) << 4));
                ldm_x4_t(bG[p], Bgb + off);
                ldm_x4_t(bU[p], Bub + off);
            }
            #pragma unroll
            for (int mt = 0; mt < 4; mt++)
                #pragma unroll
                for (int nt = 0; nt < 4; nt++) {
                    mma16816(accG[mt][nt], a[mt], &bG[nt >> 1][(nt & 1) * 2]);
                    mma16816(accU[mt][nt], a[mt], &bU[nt >> 1][(nt & 1) * 2]);
                }
        }
        __syncthreads();
        if (tid == 0 && c + G1_STG < G1_NC) issue(c + G1_STG);
    }

    // epilogue: h = silu(g+bg)*(u+bu) -> fp16 H in A-block layout
    const float* bgp = bg + e * MDIM + n0 + wn * 32;
    const float* bup = bu + e * MDIM + n0 + wn * 32;
    #pragma unroll
    for (int nt = 0; nt < 4; nt++) {
        int colb = nt * 8 + (lane & 3) * 2;
        float b_g0 = bgp[colb], b_g1 = bgp[colb + 1];
        float b_u0 = bup[colb], b_u1 = bup[colb + 1];
        int col = n0 + wn * 32 + colb;          // global H column
        int kt = col >> 6, k2 = (col & 63) * 2;
        size_t blk = (size_t)(rt * 32 + kt) * 16384;
        #pragma unroll
        for (int mt = 0; mt < 4; mt++) {
            int m = wm * 64 + mt * 16 + (lane >> 2);
            float g0 = accG[mt][nt][0] + b_g0, g1 = accG[mt][nt][1] + b_g1;
            float u0 = accU[mt][nt][0] + b_u0, u1 = accU[mt][nt][1] + b_u1;
            float h0 = g0 / (1.f + __expf(-g0)) * u0;
            float h1 = g1 / (1.f + __expf(-g1)) * u1;
            *reinterpret_cast<__half2*>((char*)g_H + blk + m * 128 + (k2 ^ ((m & 7) << 4))) =
                __floats2half2_rn(h0, h1);
            int m2 = m + 8;
            float g2 = accG[mt][nt][2] + b_g0, g3 = accG[mt][nt][3] + b_g1;
            float u2 = accU[mt][nt][2] + b_u0, u3 = accU[mt][nt][3] + b_u1;
            float h2 = g2 / (1.f + __expf(-g2)) * u2;
            float h3 = g3 / (1.f + __expf(-g3)) * u3;
            *reinterpret_cast<__half2*>((char*)g_H + blk + m2 * 128 + (k2 ^ ((m2 & 7) << 4))) =
                __floats2half2_rn(h2, h3);
        }
    }
}

// ================= GEMM2: H @ W_out -> Y fp32, 128x128, BK=64, 3-stage, 2 CTAs/SM =================
#define G2_STG 3
#define G2_NC 32
#define G2_STAGE_B 32768
#define G2_SMEM (1024 + G2_STG * G2_STAGE_B)

__global__ void __launch_bounds__(256, 2) gemm2_kernel() {
    int e = g_tile_expert[blockIdx.y];
    if (e < 0) return;
    int rt = blockIdx.y, nt_ = blockIdx.x;
    int row0 = rt * 128, n0 = nt_ * 128;
    extern __shared__ char smc[];
    uint32_t sb = smem_u32(smc);
    int tid = threadIdx.x, lane = tid & 31, w = tid >> 5;
    int wm = w >> 2, wn = w & 3;

    const char* Ablk = (const char*)g_H  + (size_t)(rt * 32) * 16384;
    const char* Bblk = (const char*)g_Wo + (size_t)((e * 8 + nt_) * 32) * 16384;

    if (tid == 0) {
        #pragma unroll
        for (int s = 0; s < G2_STG; s++) mbar_init(sb + 8 * s, 1);
    }
    __syncthreads();
    FENCE_ASYNC();

    auto issue = [&](int c) {
        int b = c % G2_STG;
        uint32_t mb = sb + 8 * b;
        uint32_t dst = sb + 1024 + b * G2_STAGE_B;
        mbar_expect_tx(mb, G2_STAGE_B);
        bulk_g2s(dst,         Ablk + (size_t)c * 16384, 16384, mb);
        bulk_g2s(dst + 16384, Bblk + (size_t)c * 16384, 16384, mb);
    };
    if (tid == 0) { issue(0); issue(1); issue(2); }

    float acc[4][4][4];
    #pragma unroll
    for (int mt = 0; mt < 4; mt++)
        #pragma unroll
        for (int nt = 0; nt < 4; nt++)
            #pragma unroll
            for (int q = 0; q < 4; q++) acc[mt][nt][q] = 0.f;

    for (int c = 0; c < G2_NC; c++) {
        mbar_wait(sb + 8 * (c % G2_STG), (c / G2_STG) & 1);
        uint32_t Ab = sb + 1024 + (c % G2_STG) * G2_STAGE_B;
        uint32_t Bb = Ab + 16384;
        #pragma unroll
        for (int kk = 0; kk < 64; kk += 16) {
            uint32_t a[4][4];
            #pragma unroll
            for (int mt = 0; mt < 4; mt++) {
                int m = wm * 64 + mt * 16 + (lane & 15);
                int colk = kk + (lane >> 4) * 8;
                ldm_x4(a[mt], Ab + m * 128 + ((colk * 2) ^ ((m & 7) << 4)));
            }
            uint32_t bB[2][4];
            #pragma unroll
            for (int p = 0; p < 2; p++) {
                int krow = kk + (lane & 15);
                int coln = wn * 32 + p * 16 + (lane >> 4) * 8;
                ldm_x4_t(bB[p], Bb + krow * 256 + ((coln * 2) ^ ((krow & 7) << 4)));
            }
            #pragma unroll
            for (int mt = 0; mt < 4; mt++)
                #pragma unroll
                for (int nt = 0; nt < 4; nt++)
                    mma16816(acc[mt][nt], a[mt], &bB[nt >> 1][(nt & 1) * 2]);
        }
        __syncthreads();
        if (tid == 0 && c + G2_STG < G2_NC) issue(c + G2_STG);
    }

    // epilogue: fp32 Y store (linear)
    #pragma unroll
    for (int nt = 0; nt < 4; nt++) {
        int colb = nt * 8 + (lane & 3) * 2;
        int col = n0 + wn * 32 + colb;
        #pragma unroll
        for (int mt = 0; mt < 4; mt++) {
            int row = row0 + wm * 64 + mt * 16 + (lane >> 2);
            float2 v0 = make_float2(acc[mt][nt][0], acc[mt][nt][1]);
            float2 v1 = make_float2(acc[mt][nt][2], acc[mt][nt][3]);
            *reinterpret_cast<float2*>(g_Y + (size_t)row * DDIM + col) = v0;
            *reinterpret_cast<float2*>(g_Y + (size_t)(row + 8) * DDIM + col) = v1;
        }
    }
}

// ---------------- combine ----------------
__global__ void combine_kernel(float* __restrict__ out, const float* __restrict__ bo) {
    int t = blockIdx.x;
    int c = threadIdx.x * 4;
    int e1 = g_tok_e[2 * t], e2 = g_tok_e[2 * t + 1];
    int r1 = g_offsets[e1] + g_tok_slot[2 * t];
    int r2 = g_offsets[e2] + g_tok_slot[2 * t + 1];
    float w1 = g_tok_w[2 * t], w2 = g_tok_w[2 * t + 1];
    float4 y1 = *reinterpret_cast<const float4*>(&g_Y[(size_t)r1 * DDIM + c]);
    float4 y2 = *reinterpret_cast<const float4*>(&g_Y[(size_t)r2 * DDIM + c]);
    float4 b1 = *reinterpret_cast<const float4*>(&bo[e1 * DDIM + c]);
    float4 b2 = *reinterpret_cast<const float4*>(&bo[e2 * DDIM + c]);
    float4 o;
    o.x = w1 * (y1.x + b1.x) + w2 * (y2.x + b2.x);
    o.y = w1 * (y1.y + b1.y) + w2 * (y2.y + b2.y);
    o.z = w1 * (y1.z + b1.z) + w2 * (y2.z + b2.z);
    o.w = w1 * (y1.w + b1.w) + w2 * (y2.w + b2.w);
    *reinterpret_cast<float4*>(&out[(size_t)t * DDIM + c]) = o;
}

// ---------------- launch ----------------
extern "C" void kernel_launch(void* const* d_in, const int* in_sizes, int n_in,
                              void* d_out, int out_size) {
    const float* residual = (const float*)d_in[0];
    const float* Wr = (const float*)d_in[1];
    const float* Wg = (const float*)d_in[2];
    const float* bg = (const float*)d_in[3];
    const float* Wu = (const float*)d_in[4];
    const float* bu = (const float*)d_in[5];
    const float* Wo = (const float*)d_in[6];
    const float* bo = (const float*)d_in[7];
    float* out = (float*)d_out;

    static bool attr_set = false;
    if (!attr_set) {
        cudaFuncSetAttribute(gemm1_kernel, cudaFuncAttributeMaxDynamicSharedMemorySize, G1_SMEM);
        cudaFuncSetAttribute(gemm2_kernel, cudaFuncAttributeMaxDynamicSharedMemorySize, G2_SMEM);
        attr_set = true;
    }

    init_kernel<<<(ROWS_PAD + 255) / 256, 256>>>();
    dim3 cg(2048, 3);
    convert_kernel<<<cg, 256>>>(Wg, Wu, Wo);
    router_kernel<<<T_TOKENS, 256>>>(residual, Wr);
    scatter_kernel<<<(T_TOKENS * 2 + 255) / 256, 256>>>();   // scan fused in (profiled slot)
    gather_kernel<<<ROWS_PAD, 128>>>(residual);
    dim3 g1(MDIM / 128, MAX_TILES);
    gemm1_kernel<<<g1, 256, G1_SMEM>>>(bg, bu);
    dim3 g2(DDIM / 128, MAX_TILES);
    gemm2_kernel<<<g2, 256, G2_SMEM>>>();
    combine_kernel<<<T_TOKENS, 256>>>(out, bo);
}

// round 8
// speedup vs baseline: 1.1022x; 1.0138x over previous
#include <cuda_runtime.h>
#include <cuda_fp16.h>
#include <cstdint>

#define T_TOKENS 4096
#define DDIM 1024
#define MDIM 2048
#define NEXP 8
#define ROWS_PAD 9216      // 72 tiles * 128 rows
#define MAX_TILES 72

// Block layout: all GEMM operands stored as 16KB blocks of (64 k) x (128 n/m),
// A blocks: 128 m x 64 k, element (m,k) at byte m*128 + ((k*2) ^ ((m&7)<<4))
// B blocks: 64 k x 128 n, element (k,n) at byte k*256 + ((n*2) ^ ((k&7)<<4))
__device__ __half g_Wg[NEXP * DDIM * MDIM];
__device__ __half g_Wu[NEXP * DDIM * MDIM];
__device__ __half g_Wo[NEXP * MDIM * DDIM];
__device__ __half g_X[ROWS_PAD * DDIM];
__device__ __half g_H[ROWS_PAD * MDIM];
__device__ float  g_Y[ROWS_PAD * DDIM];
__device__ int    g_counts[NEXP];
__device__ int    g_offsets[NEXP + 1];
__device__ int    g_tile_expert[MAX_TILES];
__device__ int    g_row_tok[ROWS_PAD];
__device__ int    g_tok_e[T_TOKENS * 2];
__device__ int    g_tok_slot[T_TOKENS * 2];
__device__ float  g_tok_w[T_TOKENS * 2];

// ---------------- helpers ----------------
__device__ __forceinline__ uint32_t smem_u32(const void* p) {
    uint32_t a;
    asm("{ .reg .u64 t; cvta.to.shared.u64 t, %1; cvt.u32.u64 %0, t; }" : "=r"(a) : "l"(p));
    return a;
}
__device__ __forceinline__ void mbar_init(uint32_t a, uint32_t cnt) {
    asm volatile("mbarrier.init.shared.b64 [%0], %1;" :: "r"(a), "r"(cnt) : "memory");
}
__device__ __forceinline__ void mbar_expect_tx(uint32_t a, uint32_t bytes) {
    asm volatile("mbarrier.arrive.expect_tx.shared.b64 _, [%0], %1;" :: "r"(a), "r"(bytes) : "memory");
}
__device__ __forceinline__ void bulk_g2s(uint32_t dst, const void* src, uint32_t bytes, uint32_t mbar) {
    asm volatile("cp.async.bulk.shared::cta.global.mbarrier::complete_tx::bytes [%0], [%1], %2, [%3];"
                 :: "r"(dst), "l"(src), "r"(bytes), "r"(mbar) : "memory");
}
__device__ __forceinline__ void mbar_wait(uint32_t a, uint32_t parity) {
    asm volatile(
        "{\n\t.reg .pred P1;\n\t"
        "W%=:\n\t"
        "mbarrier.try_wait.parity.acquire.cta.shared::cta.b64 P1, [%0], %1, 0x989680;\n\t"
        "@P1 bra.uni D%=;\n\t"
        "bra.uni W%=;\n\t"
        "D%=:\n\t}"
        :: "r"(a), "r"(parity) : "memory");
}
#define FENCE_ASYNC() asm volatile("fence.proxy.async.shared::cta;" ::: "memory")
__device__ __forceinline__ void ldm_x4(uint32_t* r, uint32_t addr) {
    asm volatile("ldmatrix.sync.aligned.m8n8.x4.shared.b16 {%0,%1,%2,%3}, [%4];"
                 : "=r"(r[0]), "=r"(r[1]), "=r"(r[2]), "=r"(r[3]) : "r"(addr));
}
__device__ __forceinline__ void ldm_x4_t(uint32_t* r, uint32_t addr) {
    asm volatile("ldmatrix.sync.aligned.m8n8.x4.trans.shared.b16 {%0,%1,%2,%3}, [%4];"
                 : "=r"(r[0]), "=r"(r[1]), "=r"(r[2]), "=r"(r[3]) : "r"(addr));
}
__device__ __forceinline__ void mma16816(float* c, const uint32_t* a, const uint32_t* b) {
    asm volatile(
        "mma.sync.aligned.m16n8k16.row.col.f32.f16.f16.f32 "
        "{%0,%1,%2,%3}, {%4,%5,%6,%7}, {%8,%9}, {%0,%1,%2,%3};"
        : "+f"(c[0]), "+f"(c[1]), "+f"(c[2]), "+f"(c[3])
        : "r"(a[0]), "r"(a[1]), "r"(a[2]), "r"(a[3]), "r"(b[0]), "r"(b[1]));
}

// ---------------- init ----------------
__global__ void init_kernel() {
    int i = blockIdx.x * blockDim.x + threadIdx.x;
    if (i < NEXP) g_counts[i] = 0;
    if (i < ROWS_PAD) g_row_tok[i] = -1;
}

// ---------------- convert: fp32 [E][K][N] -> tiled+swizzled fp16 B-blocks ----------------
__device__ __forceinline__ void convert_body(const float* __restrict__ src,
                                             __half* __restrict__ dst,
                                             int KD, int ND, int x) {
    __shared__ float tile[64][128];
    int NT = ND / 128, KT = KD / 64;
    int e = x / (NT * KT);
    int nt = (x / KT) % NT;
    int kt = x % KT;
    int k0 = kt * 64, n0 = nt * 128;
    int tid = threadIdx.x;              // 256
    const float* s = src + (size_t)e * KD * ND;
    #pragma unroll
    for (int i = 0; i < 8; i++) {
        int idx = tid + i * 256;        // 2048 float4
        int k = idx >> 5, nq = (idx & 31) * 4;
        float4 v = *reinterpret_cast<const float4*>(s + (size_t)(k0 + k) * ND + n0 + nq);
        *reinterpret_cast<float4*>(&tile[k][nq]) = v;
    }
    __syncthreads();
    uint4* out = reinterpret_cast<uint4*>(dst + (size_t)x * 8192);
    #pragma unroll
    for (int i = 0; i < 4; i++) {
        int idx = tid + i * 256;        // 1024 uint4
        int b16 = idx * 16;
        int k = b16 >> 8;
        int n = ((b16 & 255) ^ ((k & 7) << 4)) >> 1;
        __half2 h[4];
        #pragma unroll
        for (int q = 0; q < 4; q++)
            h[q] = __floats2half2_rn(tile[k][n + 2 * q], tile[k][n + 2 * q + 1]);
        out[idx] = *reinterpret_cast<uint4*>(h);
    }
}

__global__ void convert_gu_kernel(const float* __restrict__ wg,
                                  const float* __restrict__ wu) {
    if (blockIdx.y == 0) convert_body(wg, g_Wg, DDIM, MDIM, blockIdx.x);
    else                 convert_body(wu, g_Wu, DDIM, MDIM, blockIdx.x);
}
__global__ void convert_o_kernel(const float* __restrict__ wo) {
    convert_body(wo, g_Wo, MDIM, DDIM, blockIdx.x);
}

// ---------------- router: block-per-token (coalesced) ----------------
__global__ void router_kernel(const float* __restrict__ residual,
                              const float* __restrict__ Wr) {
    int t = blockIdx.x;
    __shared__ float xs[DDIM];
    __shared__ float logits[NEXP];
    int tid = threadIdx.x;
    const float* x = residual + (size_t)t * DDIM;
    for (int i = tid; i < DDIM; i += 256) xs[i] = x[i];
    __syncthreads();
    int w = tid >> 5, lane = tid & 31;
    float s = 0.f;
    for (int i = lane; i < DDIM; i += 32) s += xs[i] * Wr[i * NEXP + w];
    #pragma unroll
    for (int o = 16; o > 0; o >>= 1) s += __shfl_xor_sync(0xffffffff, s, o);
    if (lane == 0) logits[w] = s;
    __syncthreads();
    if (tid == 0) {
        float mx = logits[0];
        #pragma unroll
        for (int e = 1; e < NEXP; e++) mx = fmaxf(mx, logits[e]);
        float p[NEXP]; float sum = 0.f;
        #pragma unroll
        for (int e = 0; e < NEXP; e++) { p[e] = expf(logits[e] - mx); sum += p[e]; }
        #pragma unroll
        for (int e = 0; e < NEXP; e++) p[e] /= sum;
        int i1 = 0;
        #pragma unroll
        for (int e = 1; e < NEXP; e++) if (p[e] > p[i1]) i1 = e;
        int i2 = -1;
        #pragma unroll
        for (int e = 0; e < NEXP; e++) {
            if (e == i1) continue;
            if (i2 < 0 || p[e] > p[i2]) i2 = e;
        }
        float w1 = p[i1], w2 = p[i2];
        float inv = 1.f / (w1 + w2 + 1e-8f);
        w1 *= inv; w2 *= inv;
        int s1 = atomicAdd(&g_counts[i1], 1);
        int s2 = atomicAdd(&g_counts[i2], 1);
        g_tok_e[2 * t] = i1;     g_tok_e[2 * t + 1] = i2;
        g_tok_slot[2 * t] = s1;  g_tok_slot[2 * t + 1] = s2;
        g_tok_w[2 * t] = w1;     g_tok_w[2 * t + 1] = w2;
    }
}

// ---------------- scatter with inline scan ----------------
__global__ void scatter_kernel() {
    int i = blockIdx.x * blockDim.x + threadIdx.x;
    if (i == 0) {   // publish arrays for gemm/combine
        int off = 0, tile = 0;
        #pragma unroll
        for (int e = 0; e < NEXP; e++) {
            g_offsets[e] = off;
            int nt = (g_counts[e] + 127) >> 7;
            for (int k = 0; k < nt; k++) g_tile_expert[tile++] = e;
            off += nt << 7;
        }
        g_offsets[NEXP] = off;
        for (; tile < MAX_TILES; tile++) g_tile_expert[tile] = -1;
    }
    if (i >= T_TOKENS * 2) return;
    int e = g_tok_e[i];
    int off = 0;
    #pragma unroll
    for (int q = 0; q < NEXP; q++)
        if (q < e) off += ((g_counts[q] + 127) >> 7) << 7;
    g_row_tok[off + g_tok_slot[i]] = i >> 1;
}

// gather -> A-block layout (zero pads)
__global__ void gather_kernel(const float* __restrict__ residual) {
    int row = blockIdx.x;
    int c = threadIdx.x * 8;            // 128 threads, 8 cols each
    int tok = g_row_tok[row];
    __half2 h[4];
    if (tok < 0) {
        __half2 z = __half2half2(__float2half(0.f));
        h[0] = z; h[1] = z; h[2] = z; h[3] = z;
    } else {
        const float4* src = reinterpret_cast<const float4*>(residual + (size_t)tok * DDIM + c);
        float4 a = src[0], b = src[1];
        h[0] = __floats2half2_rn(a.x, a.y); h[1] = __floats2half2_rn(a.z, a.w);
        h[2] = __floats2half2_rn(b.x, b.y); h[3] = __floats2half2_rn(b.z, b.w);
    }
    int rt = row >> 7, m = row & 127;
    int kt = c >> 6, k = c & 63;
    reinterpret_cast<uint4*>(g_X)[(size_t)(rt * 16 + kt) * 1024 + m * 8 + ((k >> 3) ^ (m & 7))] =
        *reinterpret_cast<uint4*>(h);
}

// ================= GEMM1: fused gate+up, 128x128, BK=64, 3-stage bulk pipeline =================
#define G1_STG 3
#define G1_NC 16
#define G1_STAGE_B 49152
#define G1_SMEM (1024 + G1_STG * G1_STAGE_B)

__global__ void __launch_bounds__(256) gemm1_kernel(const float* __restrict__ bg,
                                                    const float* __restrict__ bu) {
    int e = g_tile_expert[blockIdx.y];
    if (e < 0) return;
    int rt = blockIdx.y, nt_ = blockIdx.x;
    int row0 = rt * 128, n0 = nt_ * 128;
    extern __shared__ char smc[];
    uint32_t sb = smem_u32(smc);
    int tid = threadIdx.x, lane = tid & 31, w = tid >> 5;
    int wm = w >> 2, wn = w & 3;        // 2x4 warps, 64x32 each

    const char* Ablk  = (const char*)g_X  + (size_t)(rt * 16) * 16384;
    const char* Bgblk = (const char*)g_Wg + (size_t)((e * 16 + nt_) * 16) * 16384;
    const char* Bublk = (const char*)g_Wu + (size_t)((e * 16 + nt_) * 16) * 16384;

    if (tid == 0) {
        #pragma unroll
        for (int s = 0; s < G1_STG; s++) mbar_init(sb + 8 * s, 1);
    }
    __syncthreads();
    FENCE_ASYNC();

    auto issue = [&](int c) {
        int b = c % G1_STG;
        uint32_t mb = sb + 8 * b;
        uint32_t dst = sb + 1024 + b * G1_STAGE_B;
        mbar_expect_tx(mb, G1_STAGE_B);
        bulk_g2s(dst,          Ablk  + (size_t)c * 16384, 16384, mb);
        bulk_g2s(dst + 16384,  Bgblk + (size_t)c * 16384, 16384, mb);
        bulk_g2s(dst + 32768,  Bublk + (size_t)c * 16384, 16384, mb);
    };
    if (tid == 0) { issue(0); issue(1); issue(2); }

    float accG[4][4][4], accU[4][4][4];
    #pragma unroll
    for (int mt = 0; mt < 4; mt++)
        #pragma unroll
        for (int nt = 0; nt < 4; nt++)
            #pragma unroll
            for (int q = 0; q < 4; q++) { accG[mt][nt][q] = 0.f; accU[mt][nt][q] = 0.f; }

    for (int c = 0; c < G1_NC; c++) {
        mbar_wait(sb + 8 * (c % G1_STG), (c / G1_STG) & 1);
        uint32_t Ab = sb + 1024 + (c % G1_STG) * G1_STAGE_B;
        uint32_t Bgb = Ab + 16384, Bub = Ab + 32768;
        #pragma unroll
        for (int kk = 0; kk < 64; kk += 16) {
            uint32_t a[4][4];
            #pragma unroll
            for (int mt = 0; mt < 4; mt++) {
                int m = wm * 64 + mt * 16 + (lane & 15);
                int colk = kk + (lane >> 4) * 8;
                ldm_x4(a[mt], Ab + m * 128 + ((colk * 2) ^ ((m & 7) << 4)));
            }
            uint32_t bG[2][4], bU[2][4];
            #pragma unroll
            for (int p = 0; p < 2; p++) {
                int krow = kk + (lane & 15);
                int coln = wn * 32 + p * 16 + (lane >> 4) * 8;
                uint32_t off = krow * 256 + ((coln * 2) ^ ((krow & 7) << 4));
                ldm_x4_t(bG[p], Bgb + off);
                ldm_x4_t(bU[p], Bub + off);
            }
            #pragma unroll
            for (int mt = 0; mt < 4; mt++)
                #pragma unroll
                for (int nt = 0; nt < 4; nt++) {
                    mma16816(accG[mt][nt], a[mt], &bG[nt >> 1][(nt & 1) * 2]);
                    mma16816(accU[mt][nt], a[mt], &bU[nt >> 1][(nt & 1) * 2]);
                }
        }
        __syncthreads();
        if (tid == 0 && c + G1_STG < G1_NC) issue(c + G1_STG);
    }

    // epilogue: h = silu(g+bg)*(u+bu) -> fp16 H in A-block layout
    const float* bgp = bg + e * MDIM + n0 + wn * 32;
    const float* bup = bu + e * MDIM + n0 + wn * 32;
    #pragma unroll
    for (int nt = 0; nt < 4; nt++) {
        int colb = nt * 8 + (lane & 3) * 2;
        float b_g0 = bgp[colb], b_g1 = bgp[colb + 1];
        float b_u0 = bup[colb], b_u1 = bup[colb + 1];
        int col = n0 + wn * 32 + colb;          // global H column
        int kt = col >> 6, k2 = (col & 63) * 2;
        size_t blk = (size_t)(rt * 32 + kt) * 16384;
        #pragma unroll
        for (int mt = 0; mt < 4; mt++) {
            int m = wm * 64 + mt * 16 + (lane >> 2);
            float g0 = accG[mt][nt][0] + b_g0, g1 = accG[mt][nt][1] + b_g1;
            float u0 = accU[mt][nt][0] + b_u0, u1 = accU[mt][nt][1] + b_u1;
            float h0 = g0 / (1.f + __expf(-g0)) * u0;
            float h1 = g1 / (1.f + __expf(-g1)) * u1;
            *reinterpret_cast<__half2*>((char*)g_H + blk + m * 128 + (k2 ^ ((m & 7) << 4))) =
                __floats2half2_rn(h0, h1);
            int m2 = m + 8;
            float g2 = accG[mt][nt][2] + b_g0, g3 = accG[mt][nt][3] + b_g1;
            float u2 = accU[mt][nt][2] + b_u0, u3 = accU[mt][nt][3] + b_u1;
            float h2 = g2 / (1.f + __expf(-g2)) * u2;
            float h3 = g3 / (1.f + __expf(-g3)) * u3;
            *reinterpret_cast<__half2*>((char*)g_H + blk + m2 * 128 + (k2 ^ ((m2 & 7) << 4))) =
                __floats2half2_rn(h2, h3);
        }
    }
}

// ================= GEMM2: H @ W_out -> Y fp32, 128x128, BK=64, 3-stage, 2 CTAs/SM =================
#define G2_STG 3
#define G2_NC 32
#define G2_STAGE_B 32768
#define G2_SMEM (1024 + G2_STG * G2_STAGE_B)

__global__ void __launch_bounds__(256, 2) gemm2_kernel() {
    int e = g_tile_expert[blockIdx.y];
    if (e < 0) return;
    int rt = blockIdx.y, nt_ = blockIdx.x;
    int row0 = rt * 128, n0 = nt_ * 128;
    extern __shared__ char smc[];
    uint32_t sb = smem_u32(smc);
    int tid = threadIdx.x, lane = tid & 31, w = tid >> 5;
    int wm = w >> 2, wn = w & 3;

    const char* Ablk = (const char*)g_H  + (size_t)(rt * 32) * 16384;
    const char* Bblk = (const char*)g_Wo + (size_t)((e * 8 + nt_) * 32) * 16384;

    if (tid == 0) {
        #pragma unroll
        for (int s = 0; s < G2_STG; s++) mbar_init(sb + 8 * s, 1);
    }
    __syncthreads();
    FENCE_ASYNC();

    auto issue = [&](int c) {
        int b = c % G2_STG;
        uint32_t mb = sb + 8 * b;
        uint32_t dst = sb + 1024 + b * G2_STAGE_B;
        mbar_expect_tx(mb, G2_STAGE_B);
        bulk_g2s(dst,         Ablk + (size_t)c * 16384, 16384, mb);
        bulk_g2s(dst + 16384, Bblk + (size_t)c * 16384, 16384, mb);
    };
    if (tid == 0) { issue(0); issue(1); issue(2); }

    float acc[4][4][4];
    #pragma unroll
    for (int mt = 0; mt < 4; mt++)
        #pragma unroll
        for (int nt = 0; nt < 4; nt++)
            #pragma unroll
            for (int q = 0; q < 4; q++) acc[mt][nt][q] = 0.f;

    for (int c = 0; c < G2_NC; c++) {
        mbar_wait(sb + 8 * (c % G2_STG), (c / G2_STG) & 1);
        uint32_t Ab = sb + 1024 + (c % G2_STG) * G2_STAGE_B;
        uint32_t Bb = Ab + 16384;
        #pragma unroll
        for (int kk = 0; kk < 64; kk += 16) {
            uint32_t a[4][4];
            #pragma unroll
            for (int mt = 0; mt < 4; mt++) {
                int m = wm * 64 + mt * 16 + (lane & 15);
                int colk = kk + (lane >> 4) * 8;
                ldm_x4(a[mt], Ab + m * 128 + ((colk * 2) ^ ((m & 7) << 4)));
            }
            uint32_t bB[2][4];
            #pragma unroll
            for (int p = 0; p < 2; p++) {
                int krow = kk + (lane & 15);
                int coln = wn * 32 + p * 16 + (lane >> 4) * 8;
                ldm_x4_t(bB[p], Bb + krow * 256 + ((coln * 2) ^ ((krow & 7) << 4)));
            }
            #pragma unroll
            for (int mt = 0; mt < 4; mt++)
                #pragma unroll
                for (int nt = 0; nt < 4; nt++)
                    mma16816(acc[mt][nt], a[mt], &bB[nt >> 1][(nt & 1) * 2]);
        }
        __syncthreads();
        if (tid == 0 && c + G2_STG < G2_NC) issue(c + G2_STG);
    }

    // epilogue: fp32 Y store (linear)
    #pragma unroll
    for (int nt = 0; nt < 4; nt++) {
        int colb = nt * 8 + (lane & 3) * 2;
        int col = n0 + wn * 32 + colb;
        #pragma unroll
        for (int mt = 0; mt < 4; mt++) {
            int row = row0 + wm * 64 + mt * 16 + (lane >> 2);
            float2 v0 = make_float2(acc[mt][nt][0], acc[mt][nt][1]);
            float2 v1 = make_float2(acc[mt][nt][2], acc[mt][nt][3]);
            *reinterpret_cast<float2*>(g_Y + (size_t)row * DDIM + col) = v0;
            *reinterpret_cast<float2*>(g_Y + (size_t)(row + 8) * DDIM + col) = v1;
        }
    }
}

// ---------------- combine ----------------
__global__ void combine_kernel(float* __restrict__ out, const float* __restrict__ bo) {
    int t = blockIdx.x;
    int c = threadIdx.x * 4;
    int e1 = g_tok_e[2 * t], e2 = g_tok_e[2 * t + 1];
    int r1 = g_offsets[e1] + g_tok_slot[2 * t];
    int r2 = g_offsets[e2] + g_tok_slot[2 * t + 1];
    float w1 = g_tok_w[2 * t], w2 = g_tok_w[2 * t + 1];
    float4 y1 = *reinterpret_cast<const float4*>(&g_Y[(size_t)r1 * DDIM + c]);
    float4 y2 = *reinterpret_cast<const float4*>(&g_Y[(size_t)r2 * DDIM + c]);
    float4 b1 = *reinterpret_cast<const float4*>(&bo[e1 * DDIM + c]);
    float4 b2 = *reinterpret_cast<const float4*>(&bo[e2 * DDIM + c]);
    float4 o;
    o.x = w1 * (y1.x + b1.x) + w2 * (y2.x + b2.x);
    o.y = w1 * (y1.y + b1.y) + w2 * (y2.y + b2.y);
    o.z = w1 * (y1.z + b1.z) + w2 * (y2.z + b2.z);
    o.w = w1 * (y1.w + b1.w) + w2 * (y2.w + b2.w);
    *reinterpret_cast<float4*>(&out[(size_t)t * DDIM + c]) = o;
}

// ---------------- launch: fork/join convert onto a side stream ----------------
extern "C" void kernel_launch(void* const* d_in, const int* in_sizes, int n_in,
                              void* d_out, int out_size) {
    const float* residual = (const float*)d_in[0];
    const float* Wr = (const float*)d_in[1];
    const float* Wg = (const float*)d_in[2];
    const float* bg = (const float*)d_in[3];
    const float* Wu = (const float*)d_in[4];
    const float* bu = (const float*)d_in[5];
    const float* Wo = (const float*)d_in[6];
    const float* bo = (const float*)d_in[7];
    float* out = (float*)d_out;

    static cudaStream_t s2 = nullptr;
    static cudaEvent_t ev_fork = nullptr, ev_gu = nullptr, ev_o = nullptr;
    if (!s2) {
        cudaStreamCreateWithFlags(&s2, cudaStreamNonBlocking);
        cudaEventCreateWithFlags(&ev_fork, cudaEventDisableTiming);
        cudaEventCreateWithFlags(&ev_gu, cudaEventDisableTiming);
        cudaEventCreateWithFlags(&ev_o, cudaEventDisableTiming);
        cudaFuncSetAttribute(gemm1_kernel, cudaFuncAttributeMaxDynamicSharedMemorySize, G1_SMEM);
        cudaFuncSetAttribute(gemm2_kernel, cudaFuncAttributeMaxDynamicSharedMemorySize, G2_SMEM);
    }

    // main: init -> router -> scatter -> gather          (token chain)
    // s2:   convert_gu -> convert_o                      (weight chain)
    init_kernel<<<(ROWS_PAD + 255) / 256, 256>>>();
    cudaEventRecord(ev_fork, 0);
    cudaStreamWaitEvent(s2, ev_fork, 0);
    {
        dim3 cg(2048, 2);
        convert_gu_kernel<<<cg, 256, 0, s2>>>(Wg, Wu);
        cudaEventRecord(ev_gu, s2);
        convert_o_kernel<<<2048, 256, 0, s2>>>(Wo);
        cudaEventRecord(ev_o, s2);
    }
    router_kernel<<<T_TOKENS, 256>>>(residual, Wr);
    scatter_kernel<<<(T_TOKENS * 2 + 255) / 256, 256>>>();
    gather_kernel<<<ROWS_PAD, 128>>>(residual);

    cudaStreamWaitEvent(0, ev_gu, 0);                    // join: gate/up weights ready
    dim3 g1(MDIM / 128, MAX_TILES);
    gemm1_kernel<<<g1, 256, G1_SMEM>>>(bg, bu);
    cudaStreamWaitEvent(0, ev_o, 0);                     // join: out weights ready
    dim3 g2(DDIM / 128, MAX_TILES);
    gemm2_kernel<<<g2, 256, G2_SMEM>>>();
    combine_kernel<<<T_TOKENS, 256>>>(out, bo);
}

// round 9
// speedup vs baseline: 1.1042x; 1.0018x over previous
#include <cuda_runtime.h>
#include <cuda_fp16.h>
#include <cstdint>

#define T_TOKENS 4096
#define DDIM 1024
#define MDIM 2048
#define NEXP 8
#define ROWS_PAD 9216      // 72 tiles * 128 rows
#define MAX_TILES 72

// Block layout: all GEMM operands stored as 16KB blocks of (64 k) x (128 n/m),
// A blocks: 128 m x 64 k, element (m,k) at byte m*128 + ((k*2) ^ ((m&7)<<4))
// B blocks: 64 k x 128 n, element (k,n) at byte k*256 + ((n*2) ^ ((k&7)<<4))
__device__ __half g_Wg[NEXP * DDIM * MDIM];
__device__ __half g_Wu[NEXP * DDIM * MDIM];
__device__ __half g_Wo[NEXP * MDIM * DDIM];
__device__ __half g_X[ROWS_PAD * DDIM];
__device__ __half g_H[ROWS_PAD * MDIM];
__device__ float  g_Y[ROWS_PAD * DDIM];
__device__ int    g_counts[NEXP];
__device__ int    g_offsets[NEXP + 1];
__device__ int    g_tile_expert[MAX_TILES];
__device__ int    g_row_tok[ROWS_PAD];
__device__ int    g_tok_e[T_TOKENS * 2];
__device__ int    g_tok_slot[T_TOKENS * 2];
__device__ float  g_tok_w[T_TOKENS * 2];

// ---------------- helpers ----------------
__device__ __forceinline__ uint32_t smem_u32(const void* p) {
    uint32_t a;
    asm("{ .reg .u64 t; cvta.to.shared.u64 t, %1; cvt.u32.u64 %0, t; }" : "=r"(a) : "l"(p));
    return a;
}
__device__ __forceinline__ void mbar_init(uint32_t a, uint32_t cnt) {
    asm volatile("mbarrier.init.shared.b64 [%0], %1;" :: "r"(a), "r"(cnt) : "memory");
}
__device__ __forceinline__ void mbar_expect_tx(uint32_t a, uint32_t bytes) {
    asm volatile("mbarrier.arrive.expect_tx.shared.b64 _, [%0], %1;" :: "r"(a), "r"(bytes) : "memory");
}
__device__ __forceinline__ void bulk_g2s(uint32_t dst, const void* src, uint32_t bytes, uint32_t mbar) {
    asm volatile("cp.async.bulk.shared::cta.global.mbarrier::complete_tx::bytes [%0], [%1], %2, [%3];"
                 :: "r"(dst), "l"(src), "r"(bytes), "r"(mbar) : "memory");
}
__device__ __forceinline__ void mbar_wait(uint32_t a, uint32_t parity) {
    asm volatile(
        "{\n\t.reg .pred P1;\n\t"
        "W%=:\n\t"
        "mbarrier.try_wait.parity.acquire.cta.shared::cta.b64 P1, [%0], %1, 0x989680;\n\t"
        "@P1 bra.uni D%=;\n\t"
        "bra.uni W%=;\n\t"
        "D%=:\n\t}"
        :: "r"(a), "r"(parity) : "memory");
}
#define FENCE_ASYNC() asm volatile("fence.proxy.async.shared::cta;" ::: "memory")
__device__ __forceinline__ void ldm_x4(uint32_t* r, uint32_t addr) {
    asm volatile("ldmatrix.sync.aligned.m8n8.x4.shared.b16 {%0,%1,%2,%3}, [%4];"
                 : "=r"(r[0]), "=r"(r[1]), "=r"(r[2]), "=r"(r[3]) : "r"(addr));
}
__device__ __forceinline__ void ldm_x4_t(uint32_t* r, uint32_t addr) {
    asm volatile("ldmatrix.sync.aligned.m8n8.x4.trans.shared.b16 {%0,%1,%2,%3}, [%4];"
                 : "=r"(r[0]), "=r"(r[1]), "=r"(r[2]), "=r"(r[3]) : "r"(addr));
}
__device__ __forceinline__ void mma16816(float* c, const uint32_t* a, const uint32_t* b) {
    asm volatile(
        "mma.sync.aligned.m16n8k16.row.col.f32.f16.f16.f32 "
        "{%0,%1,%2,%3}, {%4,%5,%6,%7}, {%8,%9}, {%0,%1,%2,%3};"
        : "+f"(c[0]), "+f"(c[1]), "+f"(c[2]), "+f"(c[3])
        : "r"(a[0]), "r"(a[1]), "r"(a[2]), "r"(a[3]), "r"(b[0]), "r"(b[1]));
}

// ---------------- init ----------------
__global__ void init_kernel() {
    int i = blockIdx.x * blockDim.x + threadIdx.x;
    if (i < NEXP) g_counts[i] = 0;
    if (i < ROWS_PAD) g_row_tok[i] = -1;
}

// ---------------- convert: fp32 [E][K][N] -> tiled+swizzled fp16 B-blocks ----------------
__device__ __forceinline__ void convert_body(const float* __restrict__ src,
                                             __half* __restrict__ dst,
                                             int KD, int ND, int x) {
    __shared__ float tile[64][128];
    int NT = ND / 128, KT = KD / 64;
    int e = x / (NT * KT);
    int nt = (x / KT) % NT;
    int kt = x % KT;
    int k0 = kt * 64, n0 = nt * 128;
    int tid = threadIdx.x;              // 256
    const float* s = src + (size_t)e * KD * ND;
    #pragma unroll
    for (int i = 0; i < 8; i++) {
        int idx = tid + i * 256;        // 2048 float4
        int k = idx >> 5, nq = (idx & 31) * 4;
        float4 v = *reinterpret_cast<const float4*>(s + (size_t)(k0 + k) * ND + n0 + nq);
        *reinterpret_cast<float4*>(&tile[k][nq]) = v;
    }
    __syncthreads();
    uint4* out = reinterpret_cast<uint4*>(dst + (size_t)x * 8192);
    #pragma unroll
    for (int i = 0; i < 4; i++) {
        int idx = tid + i * 256;        // 1024 uint4
        int b16 = idx * 16;
        int k = b16 >> 8;
        int n = ((b16 & 255) ^ ((k & 7) << 4)) >> 1;
        __half2 h[4];
        #pragma unroll
        for (int q = 0; q < 4; q++)
            h[q] = __floats2half2_rn(tile[k][n + 2 * q], tile[k][n + 2 * q + 1]);
        out[idx] = *reinterpret_cast<uint4*>(h);
    }
}

__global__ void convert_gu_kernel(const float* __restrict__ wg,
                                  const float* __restrict__ wu) {
    if (blockIdx.y == 0) convert_body(wg, g_Wg, DDIM, MDIM, blockIdx.x);
    else                 convert_body(wu, g_Wu, DDIM, MDIM, blockIdx.x);
}
__global__ void convert_o_kernel(const float* __restrict__ wo) {
    convert_body(wo, g_Wo, MDIM, DDIM, blockIdx.x);
}

// ---------------- router: 16 tokens/block, Wr transposed in smem, conflict-free LDS ----------------
#define RT_TPB 16
__global__ void __launch_bounds__(256) router_kernel(const float* __restrict__ residual,
                                                     const float* __restrict__ Wr) {
    __shared__ float wrT[NEXP][DDIM];       // 32 KB, transposed
    __shared__ float xs[DDIM];              // 4 KB
    __shared__ float logits[NEXP];
    int tid = threadIdx.x, w = tid >> 5, lane = tid & 31;
    // stage Wr [D][E] -> wrT[e][d], coalesced global reads
    #pragma unroll
    for (int i = 0; i < 32; i++) {
        int idx = tid + i * 256;            // 8192
        wrT[idx & 7][idx >> 3] = Wr[idx];
    }
    __syncthreads();
    const float4* wr4 = reinterpret_cast<const float4*>(&wrT[w][0]);
    for (int tt = 0; tt < RT_TPB; tt++) {
        int t = blockIdx.x * RT_TPB + tt;
        reinterpret_cast<float4*>(xs)[tid] =
            reinterpret_cast<const float4*>(residual + (size_t)t * DDIM)[tid];
        __syncthreads();
        const float4* xs4 = reinterpret_cast<const float4*>(xs);
        float s = 0.f;
        #pragma unroll
        for (int j = 0; j < 8; j++) {
            float4 xv = xs4[j * 32 + lane];
            float4 wv = wr4[j * 32 + lane];
            s += xv.x * wv.x + xv.y * wv.y + xv.z * wv.z + xv.w * wv.w;
        }
        #pragma unroll
        for (int o = 16; o > 0; o >>= 1) s += __shfl_xor_sync(0xffffffff, s, o);
        if (lane == 0) logits[w] = s;
        __syncthreads();
        if (tid == 0) {
            float mx = logits[0];
            #pragma unroll
            for (int e = 1; e < NEXP; e++) mx = fmaxf(mx, logits[e]);
            float p[NEXP]; float sum = 0.f;
            #pragma unroll
            for (int e = 0; e < NEXP; e++) { p[e] = expf(logits[e] - mx); sum += p[e]; }
            #pragma unroll
            for (int e = 0; e < NEXP; e++) p[e] /= sum;
            int i1 = 0;
            #pragma unroll
            for (int e = 1; e < NEXP; e++) if (p[e] > p[i1]) i1 = e;
            int i2 = -1;
            #pragma unroll
            for (int e = 0; e < NEXP; e++) {
                if (e == i1) continue;
                if (i2 < 0 || p[e] > p[i2]) i2 = e;
            }
            float w1 = p[i1], w2 = p[i2];
            float inv = 1.f / (w1 + w2 + 1e-8f);
            w1 *= inv; w2 *= inv;
            int s1 = atomicAdd(&g_counts[i1], 1);
            int s2 = atomicAdd(&g_counts[i2], 1);
            g_tok_e[2 * t] = i1;     g_tok_e[2 * t + 1] = i2;
            g_tok_slot[2 * t] = s1;  g_tok_slot[2 * t + 1] = s2;
            g_tok_w[2 * t] = w1;     g_tok_w[2 * t + 1] = w2;
        }
        __syncthreads();   // protect xs/logits before next token overwrites
    }
}

// ---------------- scatter with inline scan ----------------
__global__ void scatter_kernel() {
    int i = blockIdx.x * blockDim.x + threadIdx.x;
    if (i == 0) {   // publish arrays for gemm/combine
        int off = 0, tile = 0;
        #pragma unroll
        for (int e = 0; e < NEXP; e++) {
            g_offsets[e] = off;
            int nt = (g_counts[e] + 127) >> 7;
            for (int k = 0; k < nt; k++) g_tile_expert[tile++] = e;
            off += nt << 7;
        }
        g_offsets[NEXP] = off;
        for (; tile < MAX_TILES; tile++) g_tile_expert[tile] = -1;
    }
    if (i >= T_TOKENS * 2) return;
    int e = g_tok_e[i];
    int off = 0;
    #pragma unroll
    for (int q = 0; q < NEXP; q++)
        if (q < e) off += ((g_counts[q] + 127) >> 7) << 7;
    g_row_tok[off + g_tok_slot[i]] = i >> 1;
}

// gather -> A-block layout (zero pads)
__global__ void gather_kernel(const float* __restrict__ residual) {
    int row = blockIdx.x;
    int c = threadIdx.x * 8;            // 128 threads, 8 cols each
    int tok = g_row_tok[row];
    __half2 h[4];
    if (tok < 0) {
        __half2 z = __half2half2(__float2half(0.f));
        h[0] = z; h[1] = z; h[2] = z; h[3] = z;
    } else {
        const float4* src = reinterpret_cast<const float4*>(residual + (size_t)tok * DDIM + c);
        float4 a = src[0], b = src[1];
        h[0] = __floats2half2_rn(a.x, a.y); h[1] = __floats2half2_rn(a.z, a.w);
        h[2] = __floats2half2_rn(b.x, b.y); h[3] = __floats2half2_rn(b.z, b.w);
    }
    int rt = row >> 7, m = row & 127;
    int kt = c >> 6, k = c & 63;
    reinterpret_cast<uint4*>(g_X)[(size_t)(rt * 16 + kt) * 1024 + m * 8 + ((k >> 3) ^ (m & 7))] =
        *reinterpret_cast<uint4*>(h);
}

// ================= GEMM1: fused gate+up, 128x128, BK=64, 3-stage bulk pipeline =================
#define G1_STG 3
#define G1_NC 16
#define G1_STAGE_B 49152
#define G1_SMEM (1024 + G1_STG * G1_STAGE_B)

__global__ void __launch_bounds__(256) gemm1_kernel(const float* __restrict__ bg,
                                                    const float* __restrict__ bu) {
    int e = g_tile_expert[blockIdx.y];
    if (e < 0) return;
    int rt = blockIdx.y, nt_ = blockIdx.x;
    int row0 = rt * 128, n0 = nt_ * 128;
    extern __shared__ char smc[];
    uint32_t sb = smem_u32(smc);
    int tid = threadIdx.x, lane = tid & 31, w = tid >> 5;
    int wm = w >> 2, wn = w & 3;        // 2x4 warps, 64x32 each

    const char* Ablk  = (const char*)g_X  + (size_t)(rt * 16) * 16384;
    const char* Bgblk = (const char*)g_Wg + (size_t)((e * 16 + nt_) * 16) * 16384;
    const char* Bublk = (const char*)g_Wu + (size_t)((e * 16 + nt_) * 16) * 16384;

    if (tid == 0) {
        #pragma unroll
        for (int s = 0; s < G1_STG; s++) mbar_init(sb + 8 * s, 1);
    }
    __syncthreads();
    FENCE_ASYNC();

    auto issue = [&](int c) {
        int b = c % G1_STG;
        uint32_t mb = sb + 8 * b;
        uint32_t dst = sb + 1024 + b * G1_STAGE_B;
        mbar_expect_tx(mb, G1_STAGE_B);
        bulk_g2s(dst,          Ablk  + (size_t)c * 16384, 16384, mb);
        bulk_g2s(dst + 16384,  Bgblk + (size_t)c * 16384, 16384, mb);
        bulk_g2s(dst + 32768,  Bublk + (size_t)c * 16384, 16384, mb);
    };
    if (tid == 0) { issue(0); issue(1); issue(2); }

    float accG[4][4][4], accU[4][4][4];
    #pragma unroll
    for (int mt = 0; mt < 4; mt++)
        #pragma unroll
        for (int nt = 0; nt < 4; nt++)
            #pragma unroll
            for (int q = 0; q < 4; q++) { accG[mt][nt][q] = 0.f; accU[mt][nt][q] = 0.f; }

    for (int c = 0; c < G1_NC; c++) {
        mbar_wait(sb + 8 * (c % G1_STG), (c / G1_STG) & 1);
        uint32_t Ab = sb + 1024 + (c % G1_STG) * G1_STAGE_B;
        uint32_t Bgb = Ab + 16384, Bub = Ab + 32768;
        #pragma unroll
        for (int kk = 0; kk < 64; kk += 16) {
            uint32_t a[4][4];
            #pragma unroll
            for (int mt = 0; mt < 4; mt++) {
                int m = wm * 64 + mt * 16 + (lane & 15);
                int colk = kk + (lane >> 4) * 8;
                ldm_x4(a[mt], Ab + m * 128 + ((colk * 2) ^ ((m & 7) << 4)));
            }
            uint32_t bG[2][4], bU[2][4];
            #pragma unroll
            for (int p = 0; p < 2; p++) {
                int krow = kk + (lane & 15);
                int coln = wn * 32 + p * 16 + (lane >> 4) * 8;
                uint32_t off = krow * 256 + ((coln * 2) ^ ((krow & 7) << 4));
                ldm_x4_t(bG[p], Bgb + off);
                ldm_x4_t(bU[p], Bub + off);
            }
            #pragma unroll
            for (int mt = 0; mt < 4; mt++)
                #pragma unroll
                for (int nt = 0; nt < 4; nt++) {
                    mma16816(accG[mt][nt], a[mt], &bG[nt >> 1][(nt & 1) * 2]);
                    mma16816(accU[mt][nt], a[mt], &bU[nt >> 1][(nt & 1) * 2]);
                }
        }
        __syncthreads();
        if (tid == 0 && c + G1_STG < G1_NC) issue(c + G1_STG);
    }

    // epilogue: h = silu(g+bg)*(u+bu) -> fp16 H in A-block layout
    const float* bgp = bg + e * MDIM + n0 + wn * 32;
    const float* bup = bu + e * MDIM + n0 + wn * 32;
    #pragma unroll
    for (int nt = 0; nt < 4; nt++) {
        int colb = nt * 8 + (lane & 3) * 2;
        float b_g0 = bgp[colb], b_g1 = bgp[colb + 1];
        float b_u0 = bup[colb], b_u1 = bup[colb + 1];
        int col = n0 + wn * 32 + colb;          // global H column
        int kt = col >> 6, k2 = (col & 63) * 2;
        size_t blk = (size_t)(rt * 32 + kt) * 16384;
        #pragma unroll
        for (int mt = 0; mt < 4; mt++) {
            int m = wm * 64 + mt * 16 + (lane >> 2);
            float g0 = accG[mt][nt][0] + b_g0, g1 = accG[mt][nt][1] + b_g1;
            float u0 = accU[mt][nt][0] + b_u0, u1 = accU[mt][nt][1] + b_u1;
            float h0 = g0 / (1.f + __expf(-g0)) * u0;
            float h1 = g1 / (1.f + __expf(-g1)) * u1;
            *reinterpret_cast<__half2*>((char*)g_H + blk + m * 128 + (k2 ^ ((m & 7) << 4))) =
                __floats2half2_rn(h0, h1);
            int m2 = m + 8;
            float g2 = accG[mt][nt][2] + b_g0, g3 = accG[mt][nt][3] + b_g1;
            float u2 = accU[mt][nt][2] + b_u0, u3 = accU[mt][nt][3] + b_u1;
            float h2 = g2 / (1.f + __expf(-g2)) * u2;
            float h3 = g3 / (1.f + __expf(-g3)) * u3;
            *reinterpret_cast<__half2*>((char*)g_H + blk + m2 * 128 + (k2 ^ ((m2 & 7) << 4))) =
                __floats2half2_rn(h2, h3);
        }
    }
}

// ================= GEMM2: H @ W_out -> Y fp32, 128x128, BK=64, 3-stage, 2 CTAs/SM =================
#define G2_STG 3
#define G2_NC 32
#define G2_STAGE_B 32768
#define G2_SMEM (1024 + G2_STG * G2_STAGE_B)

__global__ void __launch_bounds__(256, 2) gemm2_kernel() {
    int e = g_tile_expert[blockIdx.y];
    if (e < 0) return;
    int rt = blockIdx.y, nt_ = blockIdx.x;
    int row0 = rt * 128, n0 = nt_ * 128;
    extern __shared__ char smc[];
    uint32_t sb = smem_u32(smc);
    int tid = threadIdx.x, lane = tid & 31, w = tid >> 5;
    int wm = w >> 2, wn = w & 3;

    const char* Ablk = (const char*)g_H  + (size_t)(rt * 32) * 16384;
    const char* Bblk = (const char*)g_Wo + (size_t)((e * 8 + nt_) * 32) * 16384;

    if (tid == 0) {
        #pragma unroll
        for (int s = 0; s < G2_STG; s++) mbar_init(sb + 8 * s, 1);
    }
    __syncthreads();
    FENCE_ASYNC();

    auto issue = [&](int c) {
        int b = c % G2_STG;
        uint32_t mb = sb + 8 * b;
        uint32_t dst = sb + 1024 + b * G2_STAGE_B;
        mbar_expect_tx(mb, G2_STAGE_B);
        bulk_g2s(dst,         Ablk + (size_t)c * 16384, 16384, mb);
        bulk_g2s(dst + 16384, Bblk + (size_t)c * 16384, 16384, mb);
    };
    if (tid == 0) { issue(0); issue(1); issue(2); }

    float acc[4][4][4];
    #pragma unroll
    for (int mt = 0; mt < 4; mt++)
        #pragma unroll
        for (int nt = 0; nt < 4; nt++)
            #pragma unroll
            for (int q = 0; q < 4; q++) acc[mt][nt][q] = 0.f;

    for (int c = 0; c < G2_NC; c++) {
        mbar_wait(sb + 8 * (c % G2_STG), (c / G2_STG) & 1);
        uint32_t Ab = sb + 1024 + (c % G2_STG) * G2_STAGE_B;
        uint32_t Bb = Ab + 16384;
        #pragma unroll
        for (int kk = 0; kk < 64; kk += 16) {
            uint32_t a[4][4];
            #pragma unroll
            for (int mt = 0; mt < 4; mt++) {
                int m = wm * 64 + mt * 16 + (lane & 15);
                int colk = kk + (lane >> 4) * 8;
                ldm_x4(a[mt], Ab + m * 128 + ((colk * 2) ^ ((m & 7) << 4)));
            }
            uint32_t bB[2][4];
            #pragma unroll
            for (int p = 0; p < 2; p++) {
                int krow = kk + (lane & 15);
                int coln = wn * 32 + p * 16 + (lane >> 4) * 8;
                ldm_x4_t(bB[p], Bb + krow * 256 + ((coln * 2) ^ ((krow & 7) << 4)));
            }
            #pragma unroll
            for (int mt = 0; mt < 4; mt++)
                #pragma unroll
                for (int nt = 0; nt < 4; nt++)
                    mma16816(acc[mt][nt], a[mt], &bB[nt >> 1][(nt & 1) * 2]);
        }
        __syncthreads();
        if (tid == 0 && c + G2_STG < G2_NC) issue(c + G2_STG);
    }

    // epilogue: fp32 Y store (linear)
    #pragma unroll
    for (int nt = 0; nt < 4; nt++) {
        int colb = nt * 8 + (lane & 3) * 2;
        int col = n0 + wn * 32 + colb;
        #pragma unroll
        for (int mt = 0; mt < 4; mt++) {
            int row = row0 + wm * 64 + mt * 16 + (lane >> 2);
            float2 v0 = make_float2(acc[mt][nt][0], acc[mt][nt][1]);
            float2 v1 = make_float2(acc[mt][nt][2], acc[mt][nt][3]);
            *reinterpret_cast<float2*>(g_Y + (size_t)row * DDIM + col) = v0;
            *reinterpret_cast<float2*>(g_Y + (size_t)(row + 8) * DDIM + col) = v1;
        }
    }
}

// ---------------- combine ----------------
__global__ void combine_kernel(float* __restrict__ out, const float* __restrict__ bo) {
    int t = blockIdx.x;
    int c = threadIdx.x * 4;
    int e1 = g_tok_e[2 * t], e2 = g_tok_e[2 * t + 1];
    int r1 = g_offsets[e1] + g_tok_slot[2 * t];
    int r2 = g_offsets[e2] + g_tok_slot[2 * t + 1];
    float w1 = g_tok_w[2 * t], w2 = g_tok_w[2 * t + 1];
    float4 y1 = *reinterpret_cast<const float4*>(&g_Y[(size_t)r1 * DDIM + c]);
    float4 y2 = *reinterpret_cast<const float4*>(&g_Y[(size_t)r2 * DDIM + c]);
    float4 b1 = *reinterpret_cast<const float4*>(&bo[e1 * DDIM + c]);
    float4 b2 = *reinterpret_cast<const float4*>(&bo[e2 * DDIM + c]);
    float4 o;
    o.x = w1 * (y1.x + b1.x) + w2 * (y2.x + b2.x);
    o.y = w1 * (y1.y + b1.y) + w2 * (y2.y + b2.y);
    o.z = w1 * (y1.z + b1.z) + w2 * (y2.z + b2.z);
    o.w = w1 * (y1.w + b1.w) + w2 * (y2.w + b2.w);
    *reinterpret_cast<float4*>(&out[(size_t)t * DDIM + c]) = o;
}

// ---------------- launch: fork/join convert onto a side stream ----------------
extern "C" void kernel_launch(void* const* d_in, const int* in_sizes, int n_in,
                              void* d_out, int out_size) {
    const float* residual = (const float*)d_in[0];
    const float* Wr = (const float*)d_in[1];
    const float* Wg = (const float*)d_in[2];
    const float* bg = (const float*)d_in[3];
    const float* Wu = (const float*)d_in[4];
    const float* bu = (const float*)d_in[5];
    const float* Wo = (const float*)d_in[6];
    const float* bo = (const float*)d_in[7];
    float* out = (float*)d_out;

    static cudaStream_t s2 = nullptr;
    static cudaEvent_t ev_fork = nullptr, ev_gu = nullptr, ev_o = nullptr;
    if (!s2) {
        cudaStreamCreateWithFlags(&s2, cudaStreamNonBlocking);
        cudaEventCreateWithFlags(&ev_fork, cudaEventDisableTiming);
        cudaEventCreateWithFlags(&ev_gu, cudaEventDisableTiming);
        cudaEventCreateWithFlags(&ev_o, cudaEventDisableTiming);
        cudaFuncSetAttribute(gemm1_kernel, cudaFuncAttributeMaxDynamicSharedMemorySize, G1_SMEM);
        cudaFuncSetAttribute(gemm2_kernel, cudaFuncAttributeMaxDynamicSharedMemorySize, G2_SMEM);
    }

    // main: init -> router -> scatter -> gather          (token chain)
    // s2:   convert_gu -> convert_o                      (weight chain)
    init_kernel<<<(ROWS_PAD + 255) / 256, 256>>>();
    cudaEventRecord(ev_fork, 0);
    cudaStreamWaitEvent(s2, ev_fork, 0);
    {
        dim3 cg(2048, 2);
        convert_gu_kernel<<<cg, 256, 0, s2>>>(Wg, Wu);
        cudaEventRecord(ev_gu, s2);
        convert_o_kernel<<<2048, 256, 0, s2>>>(Wo);
        cudaEventRecord(ev_o, s2);
    }
    router_kernel<<<T_TOKENS / RT_TPB, 256>>>(residual, Wr);
    scatter_kernel<<<(T_TOKENS * 2 + 255) / 256, 256>>>();
    gather_kernel<<<ROWS_PAD, 128>>>(residual);

    cudaStreamWaitEvent(0, ev_gu, 0);                    // join: gate/up weights ready
    dim3 g1(MDIM / 128, MAX_TILES);
    gemm1_kernel<<<g1, 256, G1_SMEM>>>(bg, bu);
    cudaStreamWaitEvent(0, ev_o, 0);                     // join: out weights ready
    dim3 g2(DDIM / 128, MAX_TILES);
    gemm2_kernel<<<g2, 256, G2_SMEM>>>();
    combine_kernel<<<T_TOKENS, 256>>>(out, bo);
}

// round 10
// speedup vs baseline: 1.1089x; 1.0043x over previous
#include <cuda_runtime.h>
#include <cuda_fp16.h>
#include <cstdint>

#define T_TOKENS 4096
#define DDIM 1024
#define MDIM 2048
#define NEXP 8
#define ROWS_PAD 9216      // 72 tiles * 128 rows
#define MAX_TILES 72

// Block layout: all GEMM operands stored as 16KB blocks of (64 k) x (128 n/m),
// A blocks: 128 m x 64 k, element (m,k) at byte m*128 + ((k*2) ^ ((m&7)<<4))
// B blocks: 64 k x 128 n, element (k,n) at byte k*256 + ((n*2) ^ ((k&7)<<4))
__device__ __half g_Wg[NEXP * DDIM * MDIM];
__device__ __half g_Wu[NEXP * DDIM * MDIM];
__device__ __half g_Wo[NEXP * MDIM * DDIM];
__device__ __half g_X[ROWS_PAD * DDIM];
__device__ __half g_H[ROWS_PAD * MDIM];
__device__ float  g_Y[ROWS_PAD * DDIM];
__device__ int    g_counts[NEXP];
__device__ int    g_offsets[NEXP + 1];
__device__ int    g_tile_expert[MAX_TILES];
__device__ int    g_row_tok[ROWS_PAD];
__device__ int    g_tok_e[T_TOKENS * 2];
__device__ int    g_tok_slot[T_TOKENS * 2];
__device__ float  g_tok_w[T_TOKENS * 2];

// ---------------- helpers ----------------
__device__ __forceinline__ uint32_t smem_u32(const void* p) {
    uint32_t a;
    asm("{ .reg .u64 t; cvta.to.shared.u64 t, %1; cvt.u32.u64 %0, t; }" : "=r"(a) : "l"(p));
    return a;
}
__device__ __forceinline__ void mbar_init(uint32_t a, uint32_t cnt) {
    asm volatile("mbarrier.init.shared.b64 [%0], %1;" :: "r"(a), "r"(cnt) : "memory");
}
__device__ __forceinline__ void mbar_expect_tx(uint32_t a, uint32_t bytes) {
    asm volatile("mbarrier.arrive.expect_tx.shared.b64 _, [%0], %1;" :: "r"(a), "r"(bytes) : "memory");
}
__device__ __forceinline__ void bulk_g2s(uint32_t dst, const void* src, uint32_t bytes, uint32_t mbar) {
    asm volatile("cp.async.bulk.shared::cta.global.mbarrier::complete_tx::bytes [%0], [%1], %2, [%3];"
                 :: "r"(dst), "l"(src), "r"(bytes), "r"(mbar) : "memory");
}
__device__ __forceinline__ void mbar_wait(uint32_t a, uint32_t parity) {
    asm volatile(
        "{\n\t.reg .pred P1;\n\t"
        "W%=:\n\t"
        "mbarrier.try_wait.parity.acquire.cta.shared::cta.b64 P1, [%0], %1, 0x989680;\n\t"
        "@P1 bra.uni D%=;\n\t"
        "bra.uni W%=;\n\t"
        "D%=:\n\t}"
        :: "r"(a), "r"(parity) : "memory");
}
#define FENCE_ASYNC() asm volatile("fence.proxy.async.shared::cta;" ::: "memory")
__device__ __forceinline__ void ldm_x4(uint32_t* r, uint32_t addr) {
    asm volatile("ldmatrix.sync.aligned.m8n8.x4.shared.b16 {%0,%1,%2,%3}, [%4];"
                 : "=r"(r[0]), "=r"(r[1]), "=r"(r[2]), "=r"(r[3]) : "r"(addr));
}
__device__ __forceinline__ void ldm_x4_t(uint32_t* r, uint32_t addr) {
    asm volatile("ldmatrix.sync.aligned.m8n8.x4.trans.shared.b16 {%0,%1,%2,%3}, [%4];"
                 : "=r"(r[0]), "=r"(r[1]), "=r"(r[2]), "=r"(r[3]) : "r"(addr));
}
__device__ __forceinline__ void mma16816(float* c, const uint32_t* a, const uint32_t* b) {
    asm volatile(
        "mma.sync.aligned.m16n8k16.row.col.f32.f16.f16.f32 "
        "{%0,%1,%2,%3}, {%4,%5,%6,%7}, {%8,%9}, {%0,%1,%2,%3};"
        : "+f"(c[0]), "+f"(c[1]), "+f"(c[2]), "+f"(c[3])
        : "r"(a[0]), "r"(a[1]), "r"(a[2]), "r"(a[3]), "r"(b[0]), "r"(b[1]));
}

// ---------------- init ----------------
__global__ void init_kernel() {
    int i = blockIdx.x * blockDim.x + threadIdx.x;
    if (i < NEXP) g_counts[i] = 0;
    if (i < ROWS_PAD) g_row_tok[i] = -1;
}

// ---------------- convert: fp32 [E][K][N] -> tiled+swizzled fp16 B-blocks ----------------
__device__ __forceinline__ void convert_body(const float* __restrict__ src,
                                             __half* __restrict__ dst,
                                             int KD, int ND, int x) {
    __shared__ float tile[64][128];
    int NT = ND / 128, KT = KD / 64;
    int e = x / (NT * KT);
    int nt = (x / KT) % NT;
    int kt = x % KT;
    int k0 = kt * 64, n0 = nt * 128;
    int tid = threadIdx.x;              // 256
    const float* s = src + (size_t)e * KD * ND;
    #pragma unroll
    for (int i = 0; i < 8; i++) {
        int idx = tid + i * 256;        // 2048 float4
        int k = idx >> 5, nq = (idx & 31) * 4;
        float4 v = *reinterpret_cast<const float4*>(s + (size_t)(k0 + k) * ND + n0 + nq);
        *reinterpret_cast<float4*>(&tile[k][nq]) = v;
    }
    __syncthreads();
    uint4* out = reinterpret_cast<uint4*>(dst + (size_t)x * 8192);
    #pragma unroll
    for (int i = 0; i < 4; i++) {
        int idx = tid + i * 256;        // 1024 uint4
        int k = idx >> 4;                          // output row (128 fp16 = 256B per row)
        int wb = (idx & 15) * 16;                  // byte offset within output row
        int n = (wb ^ ((k & 7) << 4)) >> 1;        // source fp16/float col, multiple of 8
        float4 v0 = *reinterpret_cast<const float4*>(&tile[k][n]);
        float4 v1 = *reinterpret_cast<const float4*>(&tile[k][n + 4]);
        __half2 h[4];
        h[0] = __floats2half2_rn(v0.x, v0.y);
        h[1] = __floats2half2_rn(v0.z, v0.w);
        h[2] = __floats2half2_rn(v1.x, v1.y);
        h[3] = __floats2half2_rn(v1.z, v1.w);
        out[idx] = *reinterpret_cast<uint4*>(h);
    }
}

__global__ void convert_gu_kernel(const float* __restrict__ wg,
                                  const float* __restrict__ wu) {
    if (blockIdx.y == 0) convert_body(wg, g_Wg, DDIM, MDIM, blockIdx.x);
    else                 convert_body(wu, g_Wu, DDIM, MDIM, blockIdx.x);
}
__global__ void convert_o_kernel(const float* __restrict__ wo) {
    convert_body(wo, g_Wo, MDIM, DDIM, blockIdx.x);
}

// ---------------- router: 16 tokens/block, Wr transposed in smem, conflict-free LDS ----------------
#define RT_TPB 16
__global__ void __launch_bounds__(256) router_kernel(const float* __restrict__ residual,
                                                     const float* __restrict__ Wr) {
    __shared__ float wrT[NEXP][DDIM];       // 32 KB, transposed
    __shared__ float xs[DDIM];              // 4 KB
    __shared__ float logits[NEXP];
    int tid = threadIdx.x, w = tid >> 5, lane = tid & 31;
    // stage Wr [D][E] -> wrT[e][d], coalesced global reads
    #pragma unroll
    for (int i = 0; i < 32; i++) {
        int idx = tid + i * 256;            // 8192
        wrT[idx & 7][idx >> 3] = Wr[idx];
    }
    __syncthreads();
    const float4* wr4 = reinterpret_cast<const float4*>(&wrT[w][0]);
    for (int tt = 0; tt < RT_TPB; tt++) {
        int t = blockIdx.x * RT_TPB + tt;
        reinterpret_cast<float4*>(xs)[tid] =
            reinterpret_cast<const float4*>(residual + (size_t)t * DDIM)[tid];
        __syncthreads();
        const float4* xs4 = reinterpret_cast<const float4*>(xs);
        float s = 0.f;
        #pragma unroll
        for (int j = 0; j < 8; j++) {
            float4 xv = xs4[j * 32 + lane];
            float4 wv = wr4[j * 32 + lane];
            s += xv.x * wv.x + xv.y * wv.y + xv.z * wv.z + xv.w * wv.w;
        }
        #pragma unroll
        for (int o = 16; o > 0; o >>= 1) s += __shfl_xor_sync(0xffffffff, s, o);
        if (lane == 0) logits[w] = s;
        __syncthreads();
        if (tid == 0) {
            float mx = logits[0];
            #pragma unroll
            for (int e = 1; e < NEXP; e++) mx = fmaxf(mx, logits[e]);
            float p[NEXP]; float sum = 0.f;
            #pragma unroll
            for (int e = 0; e < NEXP; e++) { p[e] = expf(logits[e] - mx); sum += p[e]; }
            #pragma unroll
            for (int e = 0; e < NEXP; e++) p[e] /= sum;
            int i1 = 0;
            #pragma unroll
            for (int e = 1; e < NEXP; e++) if (p[e] > p[i1]) i1 = e;
            int i2 = -1;
            #pragma unroll
            for (int e = 0; e < NEXP; e++) {
                if (e == i1) continue;
                if (i2 < 0 || p[e] > p[i2]) i2 = e;
            }
            float w1 = p[i1], w2 = p[i2];
            float inv = 1.f / (w1 + w2 + 1e-8f);
            w1 *= inv; w2 *= inv;
            int s1 = atomicAdd(&g_counts[i1], 1);
            int s2 = atomicAdd(&g_counts[i2], 1);
            g_tok_e[2 * t] = i1;     g_tok_e[2 * t + 1] = i2;
            g_tok_slot[2 * t] = s1;  g_tok_slot[2 * t + 1] = s2;
            g_tok_w[2 * t] = w1;     g_tok_w[2 * t + 1] = w2;
        }
        __syncthreads();   // protect xs/logits before next token overwrites
    }
}

// ---------------- scatter with inline scan ----------------
__global__ void scatter_kernel() {
    int i = blockIdx.x * blockDim.x + threadIdx.x;
    if (i == 0) {   // publish arrays for gemm/combine
        int off = 0, tile = 0;
        #pragma unroll
        for (int e = 0; e < NEXP; e++) {
            g_offsets[e] = off;
            int nt = (g_counts[e] + 127) >> 7;
            for (int k = 0; k < nt; k++) g_tile_expert[tile++] = e;
            off += nt << 7;
        }
        g_offsets[NEXP] = off;
        for (; tile < MAX_TILES; tile++) g_tile_expert[tile] = -1;
    }
    if (i >= T_TOKENS * 2) return;
    int e = g_tok_e[i];
    int off = 0;
    #pragma unroll
    for (int q = 0; q < NEXP; q++)
        if (q < e) off += ((g_counts[q] + 127) >> 7) << 7;
    g_row_tok[off + g_tok_slot[i]] = i >> 1;
}

// gather -> A-block layout (zero pads)
__global__ void gather_kernel(const float* __restrict__ residual) {
    int row = blockIdx.x;
    int c = threadIdx.x * 8;            // 128 threads, 8 cols each
    int tok = g_row_tok[row];
    __half2 h[4];
    if (tok < 0) {
        __half2 z = __half2half2(__float2half(0.f));
        h[0] = z; h[1] = z; h[2] = z; h[3] = z;
    } else {
        const float4* src = reinterpret_cast<const float4*>(residual + (size_t)tok * DDIM + c);
        float4 a = src[0], b = src[1];
        h[0] = __floats2half2_rn(a.x, a.y); h[1] = __floats2half2_rn(a.z, a.w);
        h[2] = __floats2half2_rn(b.x, b.y); h[3] = __floats2half2_rn(b.z, b.w);
    }
    int rt = row >> 7, m = row & 127;
    int kt = c >> 6, k = c & 63;
    reinterpret_cast<uint4*>(g_X)[(size_t)(rt * 16 + kt) * 1024 + m * 8 + ((k >> 3) ^ (m & 7))] =
        *reinterpret_cast<uint4*>(h);
}

// ================= GEMM1: fused gate+up, 128x128, BK=64, 3-stage bulk pipeline =================
#define G1_STG 3
#define G1_NC 16
#define G1_STAGE_B 49152
#define G1_SMEM (1024 + G1_STG * G1_STAGE_B)

__global__ void __launch_bounds__(256) gemm1_kernel(const float* __restrict__ bg,
                                                    const float* __restrict__ bu) {
    int e = g_tile_expert[blockIdx.y];
    if (e < 0) return;
    int rt = blockIdx.y, nt_ = blockIdx.x;
    int row0 = rt * 128, n0 = nt_ * 128;
    extern __shared__ char smc[];
    uint32_t sb = smem_u32(smc);
    int tid = threadIdx.x, lane = tid & 31, w = tid >> 5;
    int wm = w >> 2, wn = w & 3;        // 2x4 warps, 64x32 each

    const char* Ablk  = (const char*)g_X  + (size_t)(rt * 16) * 16384;
    const char* Bgblk = (const char*)g_Wg + (size_t)((e * 16 + nt_) * 16) * 16384;
    const char* Bublk = (const char*)g_Wu + (size_t)((e * 16 + nt_) * 16) * 16384;

    if (tid == 0) {
        #pragma unroll
        for (int s = 0; s < G1_STG; s++) mbar_init(sb + 8 * s, 1);
    }
    __syncthreads();
    FENCE_ASYNC();

    auto issue = [&](int c) {
        int b = c % G1_STG;
        uint32_t mb = sb + 8 * b;
        uint32_t dst = sb + 1024 + b * G1_STAGE_B;
        mbar_expect_tx(mb, G1_STAGE_B);
        bulk_g2s(dst,          Ablk  + (size_t)c * 16384, 16384, mb);
        bulk_g2s(dst + 16384,  Bgblk + (size_t)c * 16384, 16384, mb);
        bulk_g2s(dst + 32768,  Bublk + (size_t)c * 16384, 16384, mb);
    };
    if (tid == 0) { issue(0); issue(1); issue(2); }

    float accG[4][4][4], accU[4][4][4];
    #pragma unroll
    for (int mt = 0; mt < 4; mt++)
        #pragma unroll
        for (int nt = 0; nt < 4; nt++)
            #pragma unroll
            for (int q = 0; q < 4; q++) { accG[mt][nt][q] = 0.f; accU[mt][nt][q] = 0.f; }

    for (int c = 0; c < G1_NC; c++) {
        mbar_wait(sb + 8 * (c % G1_STG), (c / G1_STG) & 1);
        uint32_t Ab = sb + 1024 + (c % G1_STG) * G1_STAGE_B;
        uint32_t Bgb = Ab + 16384, Bub = Ab + 32768;
        #pragma unroll
        for (int kk = 0; kk < 64; kk += 16) {
            uint32_t a[4][4];
            #pragma unroll
            for (int mt = 0; mt < 4; mt++) {
                int m = wm * 64 + mt * 16 + (lane & 15);
                int colk = kk + (lane >> 4) * 8;
                ldm_x4(a[mt], Ab + m * 128 + ((colk * 2) ^ ((m & 7) << 4)));
            }
            uint32_t bG[2][4], bU[2][4];
            #pragma unroll
            for (int p = 0; p < 2; p++) {
                int krow = kk + (lane & 15);
                int coln = wn * 32 + p * 16 + (lane >> 4) * 8;
                uint32_t off = krow * 256 + ((coln * 2) ^ ((krow & 7) << 4));
                ldm_x4_t(bG[p], Bgb + off);
                ldm_x4_t(bU[p], Bub + off);
            }
            #pragma unroll
            for (int mt = 0; mt < 4; mt++)
                #pragma unroll
                for (int nt = 0; nt < 4; nt++) {
                    mma16816(accG[mt][nt], a[mt], &bG[nt >> 1][(nt & 1) * 2]);
                    mma16816(accU[mt][nt], a[mt], &bU[nt >> 1][(nt & 1) * 2]);
                }
        }
        __syncthreads();
        if (tid == 0 && c + G1_STG < G1_NC) issue(c + G1_STG);
    }

    // epilogue: h = silu(g+bg)*(u+bu) -> fp16 H in A-block layout
    const float* bgp = bg + e * MDIM + n0 + wn * 32;
    const float* bup = bu + e * MDIM + n0 + wn * 32;
    #pragma unroll
    for (int nt = 0; nt < 4; nt++) {
        int colb = nt * 8 + (lane & 3) * 2;
        float b_g0 = bgp[colb], b_g1 = bgp[colb + 1];
        float b_u0 = bup[colb], b_u1 = bup[colb + 1];
        int col = n0 + wn * 32 + colb;          // global H column
        int kt = col >> 6, k2 = (col & 63) * 2;
        size_t blk = (size_t)(rt * 32 + kt) * 16384;
        #pragma unroll
        for (int mt = 0; mt < 4; mt++) {
            int m = wm * 64 + mt * 16 + (lane >> 2);
            float g0 = accG[mt][nt][0] + b_g0, g1 = accG[mt][nt][1] + b_g1;
            float u0 = accU[mt][nt][0] + b_u0, u1 = accU[mt][nt][1] + b_u1;
            float h0 = g0 / (1.f + __expf(-g0)) * u0;
            float h1 = g1 / (1.f + __expf(-g1)) * u1;
            *reinterpret_cast<__half2*>((char*)g_H + blk + m * 128 + (k2 ^ ((m & 7) << 4))) =
                __floats2half2_rn(h0, h1);
            int m2 = m + 8;
            float g2 = accG[mt][nt][2] + b_g0, g3 = accG[mt][nt][3] + b_g1;
            float u2 = accU[mt][nt][2] + b_u0, u3 = accU[mt][nt][3] + b_u1;
            float h2 = g2 / (1.f + __expf(-g2)) * u2;
            float h3 = g3 / (1.f + __expf(-g3)) * u3;
            *reinterpret_cast<__half2*>((char*)g_H + blk + m2 * 128 + (k2 ^ ((m2 & 7) << 4))) =
                __floats2half2_rn(h2, h3);
        }
    }
}

// ================= GEMM2: H @ W_out -> Y fp32, 128x128, BK=64, 3-stage, 2 CTAs/SM =================
#define G2_STG 3
#define G2_NC 32
#define G2_STAGE_B 32768
#define G2_SMEM (1024 + G2_STG * G2_STAGE_B)

__global__ void __launch_bounds__(256, 2) gemm2_kernel() {
    int e = g_tile_expert[blockIdx.y];
    if (e < 0) return;
    int rt = blockIdx.y, nt_ = blockIdx.x;
    int row0 = rt * 128, n0 = nt_ * 128;
    extern __shared__ char smc[];
    uint32_t sb = smem_u32(smc);
    int tid = threadIdx.x, lane = tid & 31, w = tid >> 5;
    int wm = w >> 2, wn = w & 3;

    const char* Ablk = (const char*)g_H  + (size_t)(rt * 32) * 16384;
    const char* Bblk = (const char*)g_Wo + (size_t)((e * 8 + nt_) * 32) * 16384;

    if (tid == 0) {
        #pragma unroll
        for (int s = 0; s < G2_STG; s++) mbar_init(sb + 8 * s, 1);
    }
    __syncthreads();
    FENCE_ASYNC();

    auto issue = [&](int c) {
        int b = c % G2_STG;
        uint32_t mb = sb + 8 * b;
        uint32_t dst = sb + 1024 + b * G2_STAGE_B;
        mbar_expect_tx(mb, G2_STAGE_B);
        bulk_g2s(dst,         Ablk + (size_t)c * 16384, 16384, mb);
        bulk_g2s(dst + 16384, Bblk + (size_t)c * 16384, 16384, mb);
    };
    if (tid == 0) { issue(0); issue(1); issue(2); }

    float acc[4][4][4];
    #pragma unroll
    for (int mt = 0; mt < 4; mt++)
        #pragma unroll
        for (int nt = 0; nt < 4; nt++)
            #pragma unroll
            for (int q = 0; q < 4; q++) acc[mt][nt][q] = 0.f;

    for (int c = 0; c < G2_NC; c++) {
        mbar_wait(sb + 8 * (c % G2_STG), (c / G2_STG) & 1);
        uint32_t Ab = sb + 1024 + (c % G2_STG) * G2_STAGE_B;
        uint32_t Bb = Ab + 16384;
        #pragma unroll
        for (int kk = 0; kk < 64; kk += 16) {
            uint32_t a[4][4];
            #pragma unroll
            for (int mt = 0; mt < 4; mt++) {
                int m = wm * 64 + mt * 16 + (lane & 15);
                int colk = kk + (lane >> 4) * 8;
                ldm_x4(a[mt], Ab + m * 128 + ((colk * 2) ^ ((m & 7) << 4)));
            }
            uint32_t bB[2][4];
            #pragma unroll
            for (int p = 0; p < 2; p++) {
                int krow = kk + (lane & 15);
                int coln = wn * 32 + p * 16 + (lane >> 4) * 8;
                ldm_x4_t(bB[p], Bb + krow * 256 + ((coln * 2) ^ ((krow & 7) << 4)));
            }
            #pragma unroll
            for (int mt = 0; mt < 4; mt++)
                #pragma unroll
                for (int nt = 0; nt < 4; nt++)
                    mma16816(acc[mt][nt], a[mt], &bB[nt >> 1][(nt & 1) * 2]);
        }
        __syncthreads();
        if (tid == 0 && c + G2_STG < G2_NC) issue(c + G2_STG);
    }

    // epilogue: fp32 Y store (linear)
    #pragma unroll
    for (int nt = 0; nt < 4; nt++) {
        int colb = nt * 8 + (lane & 3) * 2;
        int col = n0 + wn * 32 + colb;
        #pragma unroll
        for (int mt = 0; mt < 4; mt++) {
            int row = row0 + wm * 64 + mt * 16 + (lane >> 2);
            float2 v0 = make_float2(acc[mt][nt][0], acc[mt][nt][1]);
            float2 v1 = make_float2(acc[mt][nt][2], acc[mt][nt][3]);
            *reinterpret_cast<float2*>(g_Y + (size_t)row * DDIM + col) = v0;
            *reinterpret_cast<float2*>(g_Y + (size_t)(row + 8) * DDIM + col) = v1;
        }
    }
}

// ---------------- combine ----------------
__global__ void combine_kernel(float* __restrict__ out, const float* __restrict__ bo) {
    int t = blockIdx.x;
    int c = threadIdx.x * 4;
    int e1 = g_tok_e[2 * t], e2 = g_tok_e[2 * t + 1];
    int r1 = g_offsets[e1] + g_tok_slot[2 * t];
    int r2 = g_offsets[e2] + g_tok_slot[2 * t + 1];
    float w1 = g_tok_w[2 * t], w2 = g_tok_w[2 * t + 1];
    float4 y1 = *reinterpret_cast<const float4*>(&g_Y[(size_t)r1 * DDIM + c]);
    float4 y2 = *reinterpret_cast<const float4*>(&g_Y[(size_t)r2 * DDIM + c]);
    float4 b1 = *reinterpret_cast<const float4*>(&bo[e1 * DDIM + c]);
    float4 b2 = *reinterpret_cast<const float4*>(&bo[e2 * DDIM + c]);
    float4 o;
    o.x = w1 * (y1.x + b1.x) + w2 * (y2.x + b2.x);
    o.y = w1 * (y1.y + b1.y) + w2 * (y2.y + b2.y);
    o.z = w1 * (y1.z + b1.z) + w2 * (y2.z + b2.z);
    o.w = w1 * (y1.w + b1.w) + w2 * (y2.w + b2.w);
    *reinterpret_cast<float4*>(&out[(size_t)t * DDIM + c]) = o;
}

// ---------------- launch: fork/join convert onto a side stream ----------------
extern "C" void kernel_launch(void* const* d_in, const int* in_sizes, int n_in,
                              void* d_out, int out_size) {
    const float* residual = (const float*)d_in[0];
    const float* Wr = (const float*)d_in[1];
    const float* Wg = (const float*)d_in[2];
    const float* bg = (const float*)d_in[3];
    const float* Wu = (const float*)d_in[4];
    const float* bu = (const float*)d_in[5];
    const float* Wo = (const float*)d_in[6];
    const float* bo = (const float*)d_in[7];
    float* out = (float*)d_out;

    static cudaStream_t s2 = nullptr;
    static cudaEvent_t ev_fork = nullptr, ev_gu = nullptr, ev_o = nullptr;
    if (!s2) {
        cudaStreamCreateWithFlags(&s2, cudaStreamNonBlocking);
        cudaEventCreateWithFlags(&ev_fork, cudaEventDisableTiming);
        cudaEventCreateWithFlags(&ev_gu, cudaEventDisableTiming);
        cudaEventCreateWithFlags(&ev_o, cudaEventDisableTiming);
        cudaFuncSetAttribute(gemm1_kernel, cudaFuncAttributeMaxDynamicSharedMemorySize, G1_SMEM);
        cudaFuncSetAttribute(gemm2_kernel, cudaFuncAttributeMaxDynamicSharedMemorySize, G2_SMEM);
    }

    // main: init -> router -> scatter -> gather          (token chain)
    // s2:   convert_gu -> convert_o                      (weight chain)
    init_kernel<<<(ROWS_PAD + 255) / 256, 256>>>();
    cudaEventRecord(ev_fork, 0);
    cudaStreamWaitEvent(s2, ev_fork, 0);
    {
        dim3 cg(2048, 2);
        convert_gu_kernel<<<cg, 256, 0, s2>>>(Wg, Wu);
        cudaEventRecord(ev_gu, s2);
        convert_o_kernel<<<2048, 256, 0, s2>>>(Wo);
        cudaEventRecord(ev_o, s2);
    }
    router_kernel<<<T_TOKENS / RT_TPB, 256>>>(residual, Wr);
    scatter_kernel<<<(T_TOKENS * 2 + 255) / 256, 256>>>();
    gather_kernel<<<ROWS_PAD, 128>>>(residual);

    cudaStreamWaitEvent(0, ev_gu, 0);                    // join: gate/up weights ready
    dim3 g1(MDIM / 128, MAX_TILES);
    gemm1_kernel<<<g1, 256, G1_SMEM>>>(bg, bu);
    cudaStreamWaitEvent(0, ev_o, 0);                     // join: out weights ready
    dim3 g2(DDIM / 128, MAX_TILES);
    gemm2_kernel<<<g2, 256, G2_SMEM>>>();
    combine_kernel<<<T_TOKENS, 256>>>(out, bo);
}